// round 5
// baseline (speedup 1.0000x reference)
#include <cuda_runtime.h>
#include <math.h>
#include <stdint.h>

// ---------------- problem constants ----------------
#define N_IMG 4
#define CIN   512
#define HH    64
#define WW    64
#define NPOS  (HH*WW)            // 4096
#define NANCH 9
#define A_TOT (NPOS*NANCH)       // 36864
#define SORT_N 65536
#define PRE_NMS  3000
#define POST_NMS 300
#define NMS_WORDS 94             // ceil(3000/32)
#define NMS_THRESH 0.7f
#define MIN_SIZE 16.0f

// ---------------- d_out layout (floats), reference return order ----------------
#define SZ_LOCS   (N_IMG*A_TOT*4)            // 589824
#define OFF_LOCS  0
#define SZ_SCORES (N_IMG*A_TOT*2)            // 294912
#define OFF_SCORES (OFF_LOCS+SZ_LOCS)        // 589824
#define SZ_ROIS   (N_IMG*POST_NMS*4)         // 4800
#define OFF_ROIS  (OFF_SCORES+SZ_SCORES)     // 884736
#define SZ_RIDX   (N_IMG*POST_NMS)           // 1200
#define OFF_RIDX  (OFF_ROIS+SZ_ROIS)         // 889536
#define OFF_ANCHOR (OFF_RIDX+SZ_RIDX)        // 890736  (size 147456)

// ---------------- device scratch ----------------
__device__ float               g_hidden[N_IMG*CIN*NPOS];        // 33.5 MB
__device__ float4              g_rois_all[N_IMG*A_TOT];         // 2.36 MB
__device__ unsigned long long  g_keys[N_IMG*SORT_N];            // 2 MB
__device__ float4              g_boxes_top[N_IMG*PRE_NMS];      // 192 KB
__device__ float               g_scores_top[N_IMG*PRE_NMS];     // 48 KB
__device__ unsigned            g_mask[(size_t)N_IMG*PRE_NMS*NMS_WORDS]; // 4.5 MB

// =================================================================
// 3x3 conv + ReLU  — packed f32x2 FMA implicit GEMM
// block: 256 thr, tile = 128 oc x (4 rows x 32 cols), CC=8 cin chunk
// per thread: 8 oc x 8 px as 4 oc-pairs (f32x2) x 8 px
// =================================================================
#define CC_CONV 8
#define OCT 128
#define RT  4
#define CT  32

__global__ __launch_bounds__(256, 2) void conv3x3_kernel(
    const float* __restrict__ x, const float* __restrict__ W1,
    const float* __restrict__ b1)
{
    __shared__ __align__(16) float Ws_s[CC_CONV*9*OCT];  // [cc][kk][oc]  36 KB
    __shared__ float Xs[CC_CONV][6][36];                 // rows+2, cols+2 (34 valid)

    const int tid = threadIdx.x;
    const int tx  = tid & 15;        // out-channel group (8 oc each)
    const int ty  = tid >> 4;        // spatial group (8 cols each)
    const int r   = ty >> 2;         // local row 0..3
    const int c0  = (ty & 3) * 8;    // local col base
    const int x0  = blockIdx.x * CT;
    const int y0  = blockIdx.y * RT;
    const int z   = blockIdx.z;
    const int img = z >> 2;
    const int oc0 = (z & 3) * OCT;

    unsigned long long acc2[4][8];   // [oc-pair][px], packed f32x2
#pragma unroll
    for (int p = 0; p < 4; p++)
#pragma unroll
        for (int j = 0; j < 8; j++) acc2[p][j] = 0ULL;

    const float* xin = x + (size_t)img * CIN * NPOS;

    for (int cc0 = 0; cc0 < CIN; cc0 += CC_CONV) {
        // load weights: CC*9*128 = 9216 floats
        for (int idx = tid; idx < CC_CONV*9*OCT; idx += 256) {
            int cc  = idx / (9*OCT);
            int rem = idx - cc*9*OCT;
            int kk  = rem >> 7;
            int oc  = rem & 127;
            Ws_s[idx] = W1[(size_t)(oc0+oc)*CIN*9 + (size_t)(cc0+cc)*9 + kk];
        }
        // load input halo tile: CC x 6 x 34 (stride 36)
        for (int idx = tid; idx < CC_CONV*6*36; idx += 256) {
            int cc  = idx / 216;
            int rem = idx - cc*216;
            int ry  = rem / 36;
            int rx  = rem - ry*36;
            float v = 0.f;
            int gy = y0 + ry - 1;
            int gx = x0 + rx - 1;
            if (rx < 34 && gy >= 0 && gy < HH && gx >= 0 && gx < WW)
                v = xin[(size_t)(cc0+cc)*NPOS + gy*WW + gx];
            Xs[cc][ry][rx] = v;
        }
        __syncthreads();

#pragma unroll 1
        for (int cc = 0; cc < CC_CONV; cc++) {
#pragma unroll
            for (int ky = 0; ky < 3; ky++) {
                // x window for this row: 10 cols, dup-packed (v,v)
                unsigned long long xd[10];
#pragma unroll
                for (int cx = 0; cx < 10; cx++) {
                    float v = Xs[cc][r+ky][c0+cx];
                    unsigned u = __float_as_uint(v);
                    asm("mov.b64 %0, {%1, %2};" : "=l"(xd[cx]) : "r"(u), "r"(u));
                }
#pragma unroll
                for (int kx = 0; kx < 3; kx++) {
                    const int kk = ky*3 + kx;
                    // 4 oc-pairs: consecutive floats -> direct 64-bit smem loads
                    const unsigned long long* wp =
                        reinterpret_cast<const unsigned long long*>(
                            &Ws_s[(cc*9+kk)*OCT + tx*8]);
                    unsigned long long w2[4];
#pragma unroll
                    for (int p = 0; p < 4; p++) w2[p] = wp[p];
#pragma unroll
                    for (int j = 0; j < 8; j++) {
#pragma unroll
                        for (int p = 0; p < 4; p++) {
                            asm("fma.rn.f32x2 %0, %1, %2, %0;"
                                : "+l"(acc2[p][j])
                                : "l"(w2[p]), "l"(xd[kx+j]));
                        }
                    }
                }
            }
        }
        __syncthreads();
    }

    // epilogue: unpack, bias, relu, vectorized store
#pragma unroll
    for (int p = 0; p < 4; p++) {
        const int ocA = oc0 + tx*8 + p*2;
        const float bA = b1[ocA];
        const float bB = b1[ocA+1];
        float lo[8], hi[8];
#pragma unroll
        for (int j = 0; j < 8; j++) {
            unsigned ul, uh;
            asm("mov.b64 {%0, %1}, %2;" : "=r"(ul), "=r"(uh) : "l"(acc2[p][j]));
            float a = __uint_as_float(ul) + bA;
            float b = __uint_as_float(uh) + bB;
            lo[j] = a > 0.f ? a : 0.f;
            hi[j] = b > 0.f ? b : 0.f;
        }
        size_t baseA = ((size_t)img*CIN + ocA)*NPOS + (y0+r)*WW + x0 + c0;
        size_t baseB = baseA + NPOS;
        reinterpret_cast<float4*>(g_hidden + baseA)[0] = make_float4(lo[0],lo[1],lo[2],lo[3]);
        reinterpret_cast<float4*>(g_hidden + baseA)[1] = make_float4(lo[4],lo[5],lo[6],lo[7]);
        reinterpret_cast<float4*>(g_hidden + baseB)[0] = make_float4(hi[0],hi[1],hi[2],hi[3]);
        reinterpret_cast<float4*>(g_hidden + baseB)[1] = make_float4(hi[4],hi[5],hi[6],hi[7]);
    }
}

// =================================================================
// 1x1 convs (loc 36 + score 18 = 54 outputs) written directly into
// d_out in the reference's reshaped layout.
// =================================================================
#define NOUT 54
__global__ __launch_bounds__(128) void conv1x1_kernel(
    const float* __restrict__ Wl, const float* __restrict__ bl,
    const float* __restrict__ Ws, const float* __restrict__ bs,
    float* __restrict__ out)
{
    __shared__ float Wc[64][NOUT];
    const int tid = threadIdx.x;
    const int img = blockIdx.y;
    const int pos = blockIdx.x * 128 + tid;

    float acc[NOUT];
#pragma unroll
    for (int o = 0; o < NOUT; o++) acc[o] = 0.f;

    const float* hid = g_hidden + (size_t)img * CIN * NPOS;

    for (int c0 = 0; c0 < CIN; c0 += 64) {
        for (int idx = tid; idx < 64*NOUT; idx += 128) {
            int c = idx / NOUT;
            int o = idx - c*NOUT;
            Wc[c][o] = (o < 36) ? Wl[(size_t)o*CIN + c0 + c]
                                : Ws[(size_t)(o-36)*CIN + c0 + c];
        }
        __syncthreads();
#pragma unroll 4
        for (int c = 0; c < 64; c++) {
            float h = hid[(size_t)(c0+c)*NPOS + pos];
#pragma unroll
            for (int o = 0; o < NOUT; o++) acc[o] += h * Wc[c][o];
        }
        __syncthreads();
    }

    float* locout = out + OFF_LOCS + (size_t)img*A_TOT*4 + (size_t)pos*36;
#pragma unroll
    for (int o = 0; o < 36; o++) locout[o] = acc[o] + bl[o];
    float* scout = out + OFF_SCORES + (size_t)img*A_TOT*2 + (size_t)pos*18;
#pragma unroll
    for (int o = 0; o < 18; o++) scout[o] = acc[36+o] + bs[o];
}

// =================================================================
// anchor generation into d_out anchor region
// =================================================================
__global__ void anchor_kernel(float* __restrict__ out)
{
    int i = blockIdx.x * blockDim.x + threadIdx.x;
    if (i >= A_TOT) return;
    int a   = i % 9;
    int pos = i / 9;
    int y = pos / WW, x = pos % WW;
    int ri = a / 3, si = a % 3;
    double rr = (ri == 0) ? 0.5 : (ri == 1 ? 1.0 : 2.0);
    double ss = (si == 0) ? 8.0 : (si == 1 ? 16.0 : 32.0);
    double h = 16.0 * ss * sqrt(rr);
    double w = 16.0 * ss * sqrt(1.0 / rr);
    float ymin = (float)(8.0 - h*0.5);
    float xmin = (float)(8.0 - w*0.5);
    float ymax = (float)(8.0 + h*0.5);
    float xmax = (float)(8.0 + w*0.5);
    float sy = (float)y * 16.0f, sx = (float)x * 16.0f;
    reinterpret_cast<float4*>(out + OFF_ANCHOR)[i] =
        make_float4(sy + ymin, sx + xmin, sy + ymax, sx + xmax);
}

// =================================================================
// proposal: loc2bbox + clip + min-size filter + fg softmax + sort key
// =================================================================
__device__ __forceinline__ float read_dim(const void* p)
{
    int v = *(const int*)p;
    if (v > 0 && v < (1 << 20)) return (float)v;   // plausibly int32
    return *(const float*)p;                        // else float bits
}

__global__ void proposal_kernel(const float* __restrict__ out,
                                const void* __restrict__ p_ih,
                                const void* __restrict__ p_iw)
{
    int t = blockIdx.x * blockDim.x + threadIdx.x;
    int img = t >> 16;          // / 65536
    int i   = t & (SORT_N - 1);
    if (img >= N_IMG) return;
    if (i >= A_TOT) { g_keys[t] = ~0ULL; return; }

    const float4 anc = reinterpret_cast<const float4*>(out + OFF_ANCHOR)[i];
    const float* loc = out + OFF_LOCS + (size_t)img*A_TOT*4 + (size_t)i*4;
    const float l0 = loc[0], l1 = loc[1], l2 = loc[2], l3 = loc[3];
    const float* sc = out + OFF_SCORES + (size_t)img*A_TOT*2 + (size_t)i*2;
    const float s0 = sc[0], s1 = sc[1];

    float h  = anc.z - anc.x, w = anc.w - anc.y;
    float cy = anc.x + 0.5f*h, cx = anc.y + 0.5f*w;
    float ncy = l0*h + cy, ncx = l1*w + cx;
    float nh  = expf(l2)*h,  nw  = expf(l3)*w;

    float fh = read_dim(p_ih), fw = read_dim(p_iw);
    float y1 = fminf(fmaxf(ncy - 0.5f*nh, 0.f), fh);
    float x1 = fminf(fmaxf(ncx - 0.5f*nw, 0.f), fw);
    float y2 = fminf(fmaxf(ncy + 0.5f*nh, 0.f), fh);
    float x2 = fminf(fmaxf(ncx + 0.5f*nw, 0.f), fw);

    bool ok = ((y2 - y1) >= MIN_SIZE) && ((x2 - x1) >= MIN_SIZE);

    float m  = fmaxf(s0, s1);
    float e0 = expf(s0 - m), e1 = expf(s1 - m);
    float fg = e1 / (e0 + e1);
    float score = ok ? fg : -INFINITY;

    g_rois_all[(size_t)img*A_TOT + i] = make_float4(y1, x1, y2, x2);

    unsigned u    = __float_as_uint(score);
    unsigned mkey = u ^ ((u >> 31) ? 0xFFFFFFFFu : 0x80000000u);   // ascending map
    unsigned dkey = ~mkey;                                          // descending
    g_keys[(size_t)img*SORT_N + i] = ((unsigned long long)dkey << 32) | (unsigned)i;
}

// =================================================================
// bitonic sort, 64-bit keys, 65536 elems per image, 4 images
// =================================================================
#define CHUNK 2048
__global__ __launch_bounds__(1024) void bitonic_local(int kstart, int fullsort)
{
    __shared__ unsigned long long sk[CHUNK];
    const int chunk = blockIdx.x;                       // 0..127
    unsigned long long* K = g_keys + (size_t)chunk * CHUNK;
    const int gbase = (chunk & 31) * CHUNK;             // index within image
    const int tid = threadIdx.x;

    sk[tid]        = K[tid];
    sk[tid + 1024] = K[tid + 1024];
    __syncthreads();

    if (fullsort) {
        for (int k = 2; k <= CHUNK; k <<= 1) {
            for (int j = k >> 1; j > 0; j >>= 1) {
                int i   = ((tid & ~(j - 1)) << 1) | (tid & (j - 1));
                int ixj = i | j;
                bool up = (((gbase + i) & k) == 0);
                unsigned long long a = sk[i], b = sk[ixj];
                if ((a > b) == up) { sk[i] = b; sk[ixj] = a; }
                __syncthreads();
            }
        }
    } else {
        const int k = kstart;
        for (int j = 1024; j > 0; j >>= 1) {
            int i   = ((tid & ~(j - 1)) << 1) | (tid & (j - 1));
            int ixj = i | j;
            bool up = (((gbase + i) & k) == 0);
            unsigned long long a = sk[i], b = sk[ixj];
            if ((a > b) == up) { sk[i] = b; sk[ixj] = a; }
            __syncthreads();
        }
    }
    K[tid]        = sk[tid];
    K[tid + 1024] = sk[tid + 1024];
}

__global__ void bitonic_global_step(int k, int j)
{
    int t   = blockIdx.x * blockDim.x + threadIdx.x;   // 4 * 32768
    int img = t >> 15;
    int tt  = t & 32767;
    int i   = ((tt & ~(j - 1)) << 1) | (tt & (j - 1));
    int ixj = i | j;
    unsigned long long* K = g_keys + (size_t)img * SORT_N;
    unsigned long long a = K[i], b = K[ixj];
    bool up = ((i & k) == 0);
    if ((a > b) == up) { K[i] = b; K[ixj] = a; }
}

// =================================================================
// gather top-3000 boxes + scores
// =================================================================
__global__ void gather_kernel()
{
    int t = blockIdx.x * blockDim.x + threadIdx.x;
    if (t >= N_IMG * PRE_NMS) return;
    int img = t / PRE_NMS;
    int i   = t - img * PRE_NMS;
    unsigned long long key = g_keys[(size_t)img*SORT_N + i];
    unsigned idx = (unsigned)(key & 0xFFFFFFFFu);
    g_boxes_top[t] = g_rois_all[(size_t)img*A_TOT + idx];
    unsigned dkey = (unsigned)(key >> 32);
    unsigned mkey = ~dkey;
    unsigned u = (mkey & 0x80000000u) ? (mkey ^ 0x80000000u) : ~mkey;
    g_scores_top[t] = __uint_as_float(u);
}

// =================================================================
// NMS suppression bitmask (3000 x 3000, only j > i bits)
// =================================================================
__global__ __launch_bounds__(64) void mask_kernel()
{
    const int img  = blockIdx.z;
    const int rowb = blockIdx.y * 64;
    const int colb = blockIdx.x * 64;
    __shared__ float4 cb[64];
    const int t = threadIdx.x;
    int col0 = colb + t;
    cb[t] = (col0 < PRE_NMS) ? g_boxes_top[(size_t)img*PRE_NMS + col0]
                             : make_float4(0.f, 0.f, 0.f, 0.f);
    __syncthreads();

    int row = rowb + t;
    if (row >= PRE_NMS) return;
    float4 rb = g_boxes_top[(size_t)img*PRE_NMS + row];
    float ra = fmaxf(rb.z - rb.x, 0.f) * fmaxf(rb.w - rb.y, 0.f);

    unsigned w0 = 0, w1 = 0;
#pragma unroll 4
    for (int c = 0; c < 64; c++) {
        int col = colb + c;
        if (col >= PRE_NMS || col <= row) continue;
        float4 b = cb[c];
        float yy1 = fmaxf(rb.x, b.x), xx1 = fmaxf(rb.y, b.y);
        float yy2 = fminf(rb.z, b.z), xx2 = fminf(rb.w, b.w);
        float inter = fmaxf(yy2 - yy1, 0.f) * fmaxf(xx2 - xx1, 0.f);
        float ba = fmaxf(b.z - b.x, 0.f) * fmaxf(b.w - b.y, 0.f);
        float iou = inter / (ra + ba - inter + 1e-9f);
        if (iou > NMS_THRESH) {
            if (c < 32) w0 |= 1u << c; else w1 |= 1u << (c - 32);
        }
    }
    unsigned* mrow = g_mask + ((size_t)img*PRE_NMS + row) * NMS_WORDS;
    int wi = colb >> 5;
    mrow[wi] = w0;
    if (wi + 1 < NMS_WORDS) mrow[wi + 1] = w1;
}

// =================================================================
// zero rois region + write roi_indices
// =================================================================
__global__ void fill_kernel(float* __restrict__ out)
{
    int t = blockIdx.x * blockDim.x + threadIdx.x;
    if (t < SZ_ROIS) out[OFF_ROIS + t] = 0.f;
    else if (t < SZ_ROIS + SZ_RIDX) {
        int i = t - SZ_ROIS;
        out[OFF_RIDX + i] = (float)(i / POST_NMS);
    }
}

// =================================================================
// sequential greedy NMS scan (1 warp per image), write kept rois
// =================================================================
__global__ void scan_kernel(float* __restrict__ out)
{
    const int img  = blockIdx.x;
    const int lane = threadIdx.x;

    unsigned sup0, sup1, sup2;
    {
        unsigned v[3];
#pragma unroll
        for (int s = 0; s < 3; s++) {
            unsigned vv = 0;
            int w = s*32 + lane;
            for (int b = 0; b < 32; b++) {
                int i = w*32 + b;
                if (i < PRE_NMS && g_scores_top[(size_t)img*PRE_NMS + i] == -INFINITY)
                    vv |= 1u << b;
            }
            v[s] = vv;
        }
        sup0 = v[0]; sup1 = v[1]; sup2 = v[2];
    }

    int keep = 0;
    const unsigned* maskbase = g_mask + (size_t)img*PRE_NMS*NMS_WORDS;

    for (int i = 0; i < PRE_NMS; i++) {
        int w = i >> 5, b = i & 31;
        int slot = w >> 5, owner = w & 31;
        unsigned myw = (slot == 0) ? sup0 : (slot == 1 ? sup1 : sup2);
        unsigned word = __shfl_sync(0xFFFFFFFFu, myw, owner);
        if (!((word >> b) & 1u)) {
            if (keep < POST_NMS && lane == 0) {
                float4 bx = g_boxes_top[(size_t)img*PRE_NMS + i];
                float* o = out + OFF_ROIS + ((size_t)img*POST_NMS + keep)*4;
                o[0] = bx.x; o[1] = bx.y; o[2] = bx.z; o[3] = bx.w;
            }
            keep++;
            const unsigned* mrow = maskbase + (size_t)i * NMS_WORDS;
            int w0i = lane, w1i = 32 + lane, w2i = 64 + lane;
            if (w0i < NMS_WORDS) sup0 |= mrow[w0i];
            if (w1i < NMS_WORDS) sup1 |= mrow[w1i];
            if (w2i < NMS_WORDS) sup2 |= mrow[w2i];
        }
    }
}

// =================================================================
// launch
// =================================================================
extern "C" void kernel_launch(void* const* d_in, const int* in_sizes, int n_in,
                              void* d_out, int out_size)
{
    const float* x   = (const float*)d_in[0];
    const void*  ih  = d_in[1];
    const void*  iw  = d_in[2];
    const float* W1  = (const float*)d_in[3];
    const float* b1  = (const float*)d_in[4];
    const float* Ws  = (const float*)d_in[5];
    const float* bs  = (const float*)d_in[6];
    const float* Wl  = (const float*)d_in[7];
    const float* bl  = (const float*)d_in[8];
    float* out = (float*)d_out;

    // 3x3 conv + relu (f32x2 packed FMA)
    conv3x3_kernel<<<dim3(WW/CT, HH/RT, N_IMG*4), 256>>>(x, W1, b1);
    // 1x1 heads -> d_out locs/scores
    conv1x1_kernel<<<dim3(NPOS/128, N_IMG), 128>>>(Wl, bl, Ws, bs, out);
    // anchors -> d_out anchor region
    anchor_kernel<<<(A_TOT + 255)/256, 256>>>(out);
    // zero rois + roi indices
    fill_kernel<<<(SZ_ROIS + SZ_RIDX + 255)/256, 256>>>(out);
    // proposals + sort keys
    proposal_kernel<<<(N_IMG*SORT_N)/256, 256>>>(out, ih, iw);

    // bitonic sort (descending score, ascending index ties)
    bitonic_local<<<128, 1024>>>(0, 1);
    for (int k = 4096; k <= SORT_N; k <<= 1) {
        for (int j = k >> 1; j >= CHUNK; j >>= 1)
            bitonic_global_step<<<(N_IMG*SORT_N/2)/256, 256>>>(k, j);
        bitonic_local<<<128, 1024>>>(k, 0);
    }

    // top-3000 gather
    gather_kernel<<<(N_IMG*PRE_NMS + 255)/256, 256>>>();
    // IoU bitmask
    mask_kernel<<<dim3(47, 47, N_IMG), 64>>>();
    // sequential NMS scan -> rois
    scan_kernel<<<N_IMG, 32>>>(out);
}

// round 7
// speedup vs baseline: 1.6541x; 1.6541x over previous
#include <cuda_runtime.h>
#include <cuda_fp16.h>
#include <math.h>
#include <stdint.h>

// ---------------- problem constants ----------------
#define N_IMG 4
#define CIN   512
#define HH    64
#define WW    64
#define NPOS  (HH*WW)            // 4096
#define NANCH 9
#define A_TOT (NPOS*NANCH)       // 36864
#define SORT_N 65536
#define PRE_NMS  3000
#define POST_NMS 300
#define NMS_WORDS 94             // ceil(3000/32)
#define NMS_THRESH 0.7f
#define MIN_SIZE 16.0f

// ---------------- d_out layout (floats), reference return order ----------------
#define SZ_LOCS   (N_IMG*A_TOT*4)            // 589824
#define OFF_LOCS  0
#define SZ_SCORES (N_IMG*A_TOT*2)            // 294912
#define OFF_SCORES (OFF_LOCS+SZ_LOCS)        // 589824
#define SZ_ROIS   (N_IMG*POST_NMS*4)         // 4800
#define OFF_ROIS  (OFF_SCORES+SZ_SCORES)     // 884736
#define SZ_RIDX   (N_IMG*POST_NMS)           // 1200
#define OFF_RIDX  (OFF_ROIS+SZ_ROIS)         // 889536
#define OFF_ANCHOR (OFF_RIDX+SZ_RIDX)        // 890736  (size 147456)

// ---------------- device scratch ----------------
__device__ float               g_hidden[N_IMG*CIN*NPOS];        // 33.5 MB
__device__ float4              g_rois_all[N_IMG*A_TOT];         // 2.36 MB
__device__ unsigned long long  g_keys[N_IMG*SORT_N];            // 2 MB
__device__ float4              g_boxes_top[N_IMG*PRE_NMS];      // 192 KB
__device__ float               g_scores_top[N_IMG*PRE_NMS];     // 48 KB
__device__ unsigned            g_mask[(size_t)N_IMG*PRE_NMS*NMS_WORDS]; // 4.5 MB

// split-fp16 weights (scaled x64), pre-swizzled smem-tile layout:
// [ot(4)][ch(72)] tiles of 16KB ([128 oc rows x 64 f16 = 128B], SW128 swizzled)
#define NCHUNK 72
__device__ uint4 g_wt_hi[4*NCHUNK*1024];   // 4.7 MB
__device__ uint4 g_wt_lo[4*NCHUNK*1024];   // 4.7 MB

#define W_SCALE 64.0f
#define W_INV   (1.0f/64.0f)

#define SWZ128(o) ((o) ^ (((o) >> 3) & 0x70))

__device__ __forceinline__ unsigned smem_u32(const void* p) {
    unsigned a;
    asm("{ .reg .u64 t; cvta.to.shared.u64 t, %1; cvt.u32.u64 %0, t; }"
        : "=r"(a) : "l"(p));
    return a;
}

__device__ __forceinline__ void ldsm4(unsigned& r0, unsigned& r1,
                                      unsigned& r2, unsigned& r3, unsigned addr)
{
    asm volatile("ldmatrix.sync.aligned.m8n8.x4.shared.b16 {%0,%1,%2,%3}, [%4];"
                 : "=r"(r0), "=r"(r1), "=r"(r2), "=r"(r3) : "r"(addr));
}

__device__ __forceinline__ void mma16816(float* c, const unsigned* a, const unsigned* b)
{
    asm volatile(
        "mma.sync.aligned.m16n8k16.row.col.f32.f16.f16.f32 "
        "{%0,%1,%2,%3}, {%4,%5,%6,%7}, {%8,%9}, {%0,%1,%2,%3};"
        : "+f"(c[0]), "+f"(c[1]), "+f"(c[2]), "+f"(c[3])
        : "r"(a[0]), "r"(a[1]), "r"(a[2]), "r"(a[3]), "r"(b[0]), "r"(b[1]));
}

// =================================================================
// weight prep: fp32 W1 [oc][cin][3][3] -> x64-scaled split fp16 hi/lo
// tiles, pre-swizzled. chunk ch = kk*8 + ccb (tap kk, cin block ccb*64)
// =================================================================
__global__ void wprep_kernel(const float* __restrict__ W1)
{
    int t = blockIdx.x * blockDim.x + threadIdx.x;
    if (t >= 4*NCHUNK*128*32) return;
    int c2 = t & 31;             // column pair
    int r  = (t >> 5) & 127;     // oc row in tile
    int tc = t >> 12;            // ot*72 + ch
    int ch = tc % NCHUNK;
    int ot = tc / NCHUNK;
    int kk  = ch >> 3;
    int ccb = ch & 7;
    int c  = c2 * 2;
    int cc = ccb*64 + c;
    int oc = ot*128 + r;

    float w0 = W1[(size_t)oc*4608 + (size_t)cc*9 + kk] * W_SCALE;
    float w1 = W1[(size_t)oc*4608 + (size_t)(cc+1)*9 + kk] * W_SCALE;
    __half h0 = __float2half_rn(w0), h1 = __float2half_rn(w1);
    __half l0 = __float2half_rn(w0 - __half2float(h0));
    __half l1 = __float2half_rn(w1 - __half2float(h1));

    unsigned off = (unsigned)(r*128 + c*2);
    off = SWZ128(off);
    size_t base = (size_t)tc * 16384;
    *reinterpret_cast<__half2*>(reinterpret_cast<char*>(g_wt_hi) + base + off) =
        __halves2half2(h0, h1);
    *reinterpret_cast<__half2*>(reinterpret_cast<char*>(g_wt_lo) + base + off) =
        __halves2half2(l0, l1);
}

// =================================================================
// HMMA split-fp16 conv: per CTA 128 oc x 128 pos (2 image rows)
// 72 chunks (9 taps x 8 cin-blocks of 64). 3 mma per tile-step:
// wh*xh + wh*xl + wl*xh, single fp32 accumulator, /64 in epilogue.
// =================================================================
#define SM_AHI 0
#define SM_ALO 16384
#define SM_BHI 32768
#define SM_BLO 49152
#define SM_CONV_TOTAL 65536

__global__ void __launch_bounds__(256, 2) conv_hmma_kernel(
    const float* __restrict__ x, const float* __restrict__ b1)
{
    extern __shared__ char smem[];
    const unsigned sbase = smem_u32(smem);
    const int tid  = threadIdx.x;
    const int wid  = tid >> 5;
    const int lane = tid & 31;
    const int ot   = blockIdx.x;          // oc tile 0..3
    const int pt   = blockIdx.y;          // pos tile 0..31
    const int img  = blockIdx.z;

    const int wm = wid >> 2;              // 0..1 : oc block of 64
    const int wn = wid & 3;               // 0..3 : pos block of 32

    const int sel = lane >> 3;            // ldmatrix matrix select 0..3
    const int l7  = lane & 7;

    // B-build thread mapping
    const int pos0 = pt * 128;
    const int y0   = pos0 >> 6;           // 2*pt
    const int n    = tid & 127;           // pos within tile
    const int half = tid >> 7;            // k half (0: c 0..31, 1: c 32..63)
    const int rowN = n >> 6;
    const int colN = n & 63;

    const float* xin = x + (size_t)img * CIN * NPOS;

    float acc[4][4][4];
#pragma unroll
    for (int mt = 0; mt < 4; mt++)
#pragma unroll
        for (int nt = 0; nt < 4; nt++)
#pragma unroll
            for (int k = 0; k < 4; k++) acc[mt][nt][k] = 0.f;

    // per-thread ldmatrix base offsets (before k-step column add)
    // A: row = wm*64 + mt*16 + (sel&1)*8 + l7 ; colb = (sel>>1)*16
    const unsigned a_row = (unsigned)(wm*64 + (sel & 1)*8 + l7);
    const unsigned a_colb = (unsigned)((sel >> 1) * 16);
    // B: row = wn*32 + (sel>>1)*8 + l7 (+16 for second x4) ; colb = (sel&1)*16
    const unsigned b_row = (unsigned)(wn*32 + (sel >> 1)*8 + l7);
    const unsigned b_colb = (unsigned)((sel & 1) * 16);

    for (int ch = 0; ch < NCHUNK; ch++) {
        // ---- A copy: pre-swizzled 16KB hi/lo tiles, linear uint4 ----
        {
            const uint4* sh = g_wt_hi + (size_t)(ot*NCHUNK + ch) * 1024;
            const uint4* sl = g_wt_lo + (size_t)(ot*NCHUNK + ch) * 1024;
            uint4* dh = reinterpret_cast<uint4*>(smem + SM_AHI);
            uint4* dl = reinterpret_cast<uint4*>(smem + SM_ALO);
#pragma unroll
            for (int i = 0; i < 4; i++) {
                dh[tid + i*256] = sh[tid + i*256];
                dl[tid + i*256] = sl[tid + i*256];
            }
        }
        // ---- B build: im2col gather + fp16 split, swizzled STS ----
        {
            const int kk  = ch >> 3;
            const int ccb = ch & 7;
            const int dy  = kk / 3 - 1;
            const int dx  = kk % 3 - 1;
            const int gy  = y0 + rowN + dy;
            const int gx  = colN + dx;
            const bool valid = (gy >= 0) && (gy < HH) && (gx >= 0) && (gx < WW);
            const float* src = xin + (size_t)(ccb*64)*NPOS + gy*WW + gx;
#pragma unroll 4
            for (int i = 0; i < 16; i++) {
                const int c = half*32 + 2*i;
                float v0 = 0.f, v1 = 0.f;
                if (valid) {
                    v0 = src[(size_t)c * NPOS];
                    v1 = src[(size_t)(c+1) * NPOS];
                }
                __half h0 = __float2half_rn(v0), h1 = __float2half_rn(v1);
                __half l0 = __float2half_rn(v0 - __half2float(h0));
                __half l1 = __float2half_rn(v1 - __half2float(h1));
                unsigned off = (unsigned)(n*128 + c*2);
                off = SWZ128(off);
                *reinterpret_cast<__half2*>(smem + SM_BHI + off) = __halves2half2(h0, h1);
                *reinterpret_cast<__half2*>(smem + SM_BLO + off) = __halves2half2(l0, l1);
            }
        }
        __syncthreads();

        // ---- mma phase: 4 k16 steps ----
#pragma unroll
        for (int ks = 0; ks < 4; ks++) {
            const unsigned kcol = (unsigned)(ks * 32);
            // B fragments: ntiles 0..3 (hi & lo)
            unsigned bh[8], bl[8];
            {
                unsigned off0 = SWZ128(b_row*128 + kcol + b_colb);
                unsigned off1 = SWZ128((b_row+16)*128 + kcol + b_colb);
                ldsm4(bh[0], bh[1], bh[2], bh[3], sbase + SM_BHI + off0);
                ldsm4(bh[4], bh[5], bh[6], bh[7], sbase + SM_BHI + off1);
                ldsm4(bl[0], bl[1], bl[2], bl[3], sbase + SM_BLO + off0);
                ldsm4(bl[4], bl[5], bl[6], bl[7], sbase + SM_BLO + off1);
            }
#pragma unroll
            for (int mt = 0; mt < 4; mt++) {
                unsigned aoff = SWZ128((a_row + mt*16)*128 + kcol + a_colb);
                unsigned ah[4], al[4];
                ldsm4(ah[0], ah[1], ah[2], ah[3], sbase + SM_AHI + aoff);
                ldsm4(al[0], al[1], al[2], al[3], sbase + SM_ALO + aoff);
#pragma unroll
                for (int nt = 0; nt < 4; nt++) {
                    mma16816(acc[mt][nt], ah, &bh[nt*2]);   // wh*xh
                    mma16816(acc[mt][nt], ah, &bl[nt*2]);   // wh*xl
                    mma16816(acc[mt][nt], al, &bh[nt*2]);   // wl*xh
                }
            }
        }
        __syncthreads();
    }

    // ---- epilogue: /64, +bias, relu, store ----
    const int mrow = lane >> 2;           // 0..7
    const int ncol = (lane & 3) * 2;      // 0,2,4,6
#pragma unroll
    for (int mt = 0; mt < 4; mt++) {
        const int ocA = ot*128 + wm*64 + mt*16 + mrow;
        const int ocB = ocA + 8;
        const float biasA = b1[ocA];
        const float biasB = b1[ocB];
#pragma unroll
        for (int nt = 0; nt < 4; nt++) {
            const int pos = pos0 + wn*32 + nt*8 + ncol;
            float v0 = acc[mt][nt][0] * W_INV + biasA;
            float v1 = acc[mt][nt][1] * W_INV + biasA;
            float v2 = acc[mt][nt][2] * W_INV + biasB;
            float v3 = acc[mt][nt][3] * W_INV + biasB;
            v0 = v0 > 0.f ? v0 : 0.f;
            v1 = v1 > 0.f ? v1 : 0.f;
            v2 = v2 > 0.f ? v2 : 0.f;
            v3 = v3 > 0.f ? v3 : 0.f;
            *reinterpret_cast<float2*>(
                g_hidden + ((size_t)img*CIN + ocA)*NPOS + pos) = make_float2(v0, v1);
            *reinterpret_cast<float2*>(
                g_hidden + ((size_t)img*CIN + ocB)*NPOS + pos) = make_float2(v2, v3);
        }
    }
}

// =================================================================
// 1x1 convs (loc 36 + score 18 = 54 outputs) written directly into
// d_out in the reference's reshaped layout.
// =================================================================
#define NOUT 54
__global__ __launch_bounds__(128) void conv1x1_kernel(
    const float* __restrict__ Wl, const float* __restrict__ bl,
    const float* __restrict__ Ws, const float* __restrict__ bs,
    float* __restrict__ out)
{
    __shared__ float Wc[64][NOUT];
    const int tid = threadIdx.x;
    const int img = blockIdx.y;
    const int pos = blockIdx.x * 128 + tid;

    float acc[NOUT];
#pragma unroll
    for (int o = 0; o < NOUT; o++) acc[o] = 0.f;

    const float* hid = g_hidden + (size_t)img * CIN * NPOS;

    for (int c0 = 0; c0 < CIN; c0 += 64) {
        for (int idx = tid; idx < 64*NOUT; idx += 128) {
            int c = idx / NOUT;
            int o = idx - c*NOUT;
            Wc[c][o] = (o < 36) ? Wl[(size_t)o*CIN + c0 + c]
                                : Ws[(size_t)(o-36)*CIN + c0 + c];
        }
        __syncthreads();
#pragma unroll 4
        for (int c = 0; c < 64; c++) {
            float h = hid[(size_t)(c0+c)*NPOS + pos];
#pragma unroll
            for (int o = 0; o < NOUT; o++) acc[o] += h * Wc[c][o];
        }
        __syncthreads();
    }

    float* locout = out + OFF_LOCS + (size_t)img*A_TOT*4 + (size_t)pos*36;
#pragma unroll
    for (int o = 0; o < 36; o++) locout[o] = acc[o] + bl[o];
    float* scout = out + OFF_SCORES + (size_t)img*A_TOT*2 + (size_t)pos*18;
#pragma unroll
    for (int o = 0; o < 18; o++) scout[o] = acc[36+o] + bs[o];
}

// =================================================================
// anchor generation into d_out anchor region
// =================================================================
__global__ void anchor_kernel(float* __restrict__ out)
{
    int i = blockIdx.x * blockDim.x + threadIdx.x;
    if (i >= A_TOT) return;
    int a   = i % 9;
    int pos = i / 9;
    int y = pos / WW, x = pos % WW;
    int ri = a / 3, si = a % 3;
    double rr = (ri == 0) ? 0.5 : (ri == 1 ? 1.0 : 2.0);
    double ss = (si == 0) ? 8.0 : (si == 1 ? 16.0 : 32.0);
    double h = 16.0 * ss * sqrt(rr);
    double w = 16.0 * ss * sqrt(1.0 / rr);
    float ymin = (float)(8.0 - h*0.5);
    float xmin = (float)(8.0 - w*0.5);
    float ymax = (float)(8.0 + h*0.5);
    float xmax = (float)(8.0 + w*0.5);
    float sy = (float)y * 16.0f, sx = (float)x * 16.0f;
    reinterpret_cast<float4*>(out + OFF_ANCHOR)[i] =
        make_float4(sy + ymin, sx + xmin, sy + ymax, sx + xmax);
}

// =================================================================
// proposal: loc2bbox + clip + min-size filter + fg softmax + sort key
// =================================================================
__device__ __forceinline__ float read_dim(const void* p)
{
    int v = *(const int*)p;
    if (v > 0 && v < (1 << 20)) return (float)v;   // plausibly int32
    return *(const float*)p;                        // else float bits
}

__global__ void proposal_kernel(const float* __restrict__ out,
                                const void* __restrict__ p_ih,
                                const void* __restrict__ p_iw)
{
    int t = blockIdx.x * blockDim.x + threadIdx.x;
    int img = t >> 16;          // / 65536
    int i   = t & (SORT_N - 1);
    if (img >= N_IMG) return;
    if (i >= A_TOT) { g_keys[t] = ~0ULL; return; }

    const float4 anc = reinterpret_cast<const float4*>(out + OFF_ANCHOR)[i];
    const float* loc = out + OFF_LOCS + (size_t)img*A_TOT*4 + (size_t)i*4;
    const float l0 = loc[0], l1 = loc[1], l2 = loc[2], l3 = loc[3];
    const float* sc = out + OFF_SCORES + (size_t)img*A_TOT*2 + (size_t)i*2;
    const float s0 = sc[0], s1 = sc[1];

    float h  = anc.z - anc.x, w = anc.w - anc.y;
    float cy = anc.x + 0.5f*h, cx = anc.y + 0.5f*w;
    float ncy = l0*h + cy, ncx = l1*w + cx;
    float nh  = expf(l2)*h,  nw  = expf(l3)*w;

    float fh = read_dim(p_ih), fw = read_dim(p_iw);
    float y1 = fminf(fmaxf(ncy - 0.5f*nh, 0.f), fh);
    float x1 = fminf(fmaxf(ncx - 0.5f*nw, 0.f), fw);
    float y2 = fminf(fmaxf(ncy + 0.5f*nh, 0.f), fh);
    float x2 = fminf(fmaxf(ncx + 0.5f*nw, 0.f), fw);

    bool ok = ((y2 - y1) >= MIN_SIZE) && ((x2 - x1) >= MIN_SIZE);

    float m  = fmaxf(s0, s1);
    float e0 = expf(s0 - m), e1 = expf(s1 - m);
    float fg = e1 / (e0 + e1);
    float score = ok ? fg : -INFINITY;

    g_rois_all[(size_t)img*A_TOT + i] = make_float4(y1, x1, y2, x2);

    unsigned u    = __float_as_uint(score);
    unsigned mkey = u ^ ((u >> 31) ? 0xFFFFFFFFu : 0x80000000u);   // ascending map
    unsigned dkey = ~mkey;                                          // descending
    g_keys[(size_t)img*SORT_N + i] = ((unsigned long long)dkey << 32) | (unsigned)i;
}

// =================================================================
// bitonic sort, 64-bit keys, 65536 elems per image, 4 images
// =================================================================
#define CHUNK 2048
__global__ __launch_bounds__(1024) void bitonic_local(int kstart, int fullsort)
{
    __shared__ unsigned long long sk[CHUNK];
    const int chunk = blockIdx.x;                       // 0..127
    unsigned long long* K = g_keys + (size_t)chunk * CHUNK;
    const int gbase = (chunk & 31) * CHUNK;             // index within image
    const int tid = threadIdx.x;

    sk[tid]        = K[tid];
    sk[tid + 1024] = K[tid + 1024];
    __syncthreads();

    if (fullsort) {
        for (int k = 2; k <= CHUNK; k <<= 1) {
            for (int j = k >> 1; j > 0; j >>= 1) {
                int i   = ((tid & ~(j - 1)) << 1) | (tid & (j - 1));
                int ixj = i | j;
                bool up = (((gbase + i) & k) == 0);
                unsigned long long a = sk[i], b = sk[ixj];
                if ((a > b) == up) { sk[i] = b; sk[ixj] = a; }
                __syncthreads();
            }
        }
    } else {
        const int k = kstart;
        for (int j = 1024; j > 0; j >>= 1) {
            int i   = ((tid & ~(j - 1)) << 1) | (tid & (j - 1));
            int ixj = i | j;
            bool up = (((gbase + i) & k) == 0);
            unsigned long long a = sk[i], b = sk[ixj];
            if ((a > b) == up) { sk[i] = b; sk[ixj] = a; }
            __syncthreads();
        }
    }
    K[tid]        = sk[tid];
    K[tid + 1024] = sk[tid + 1024];
}

__global__ void bitonic_global_step(int k, int j)
{
    int t   = blockIdx.x * blockDim.x + threadIdx.x;   // 4 * 32768
    int img = t >> 15;
    int tt  = t & 32767;
    int i   = ((tt & ~(j - 1)) << 1) | (tt & (j - 1));
    int ixj = i | j;
    unsigned long long* K = g_keys + (size_t)img * SORT_N;
    unsigned long long a = K[i], b = K[ixj];
    bool up = ((i & k) == 0);
    if ((a > b) == up) { K[i] = b; K[ixj] = a; }
}

// =================================================================
// gather top-3000 boxes + scores
// =================================================================
__global__ void gather_kernel()
{
    int t = blockIdx.x * blockDim.x + threadIdx.x;
    if (t >= N_IMG * PRE_NMS) return;
    int img = t / PRE_NMS;
    int i   = t - img * PRE_NMS;
    unsigned long long key = g_keys[(size_t)img*SORT_N + i];
    unsigned idx = (unsigned)(key & 0xFFFFFFFFu);
    g_boxes_top[t] = g_rois_all[(size_t)img*A_TOT + idx];
    unsigned dkey = (unsigned)(key >> 32);
    unsigned mkey = ~dkey;
    unsigned u = (mkey & 0x80000000u) ? (mkey ^ 0x80000000u) : ~mkey;
    g_scores_top[t] = __uint_as_float(u);
}

// =================================================================
// NMS suppression bitmask (3000 x 3000, only j > i bits)
// =================================================================
__global__ __launch_bounds__(64) void mask_kernel()
{
    const int img  = blockIdx.z;
    const int rowb = blockIdx.y * 64;
    const int colb = blockIdx.x * 64;
    __shared__ float4 cb[64];
    const int t = threadIdx.x;
    int col0 = colb + t;
    cb[t] = (col0 < PRE_NMS) ? g_boxes_top[(size_t)img*PRE_NMS + col0]
                             : make_float4(0.f, 0.f, 0.f, 0.f);
    __syncthreads();

    int row = rowb + t;
    if (row >= PRE_NMS) return;
    float4 rb = g_boxes_top[(size_t)img*PRE_NMS + row];
    float ra = fmaxf(rb.z - rb.x, 0.f) * fmaxf(rb.w - rb.y, 0.f);

    unsigned w0 = 0, w1 = 0;
#pragma unroll 4
    for (int c = 0; c < 64; c++) {
        int col = colb + c;
        if (col >= PRE_NMS || col <= row) continue;
        float4 b = cb[c];
        float yy1 = fmaxf(rb.x, b.x), xx1 = fmaxf(rb.y, b.y);
        float yy2 = fminf(rb.z, b.z), xx2 = fminf(rb.w, b.w);
        float inter = fmaxf(yy2 - yy1, 0.f) * fmaxf(xx2 - xx1, 0.f);
        float ba = fmaxf(b.z - b.x, 0.f) * fmaxf(b.w - b.y, 0.f);
        float iou = inter / (ra + ba - inter + 1e-9f);
        if (iou > NMS_THRESH) {
            if (c < 32) w0 |= 1u << c; else w1 |= 1u << (c - 32);
        }
    }
    unsigned* mrow = g_mask + ((size_t)img*PRE_NMS + row) * NMS_WORDS;
    int wi = colb >> 5;
    mrow[wi] = w0;
    if (wi + 1 < NMS_WORDS) mrow[wi + 1] = w1;
}

// =================================================================
// zero rois region + write roi_indices
// =================================================================
__global__ void fill_kernel(float* __restrict__ out)
{
    int t = blockIdx.x * blockDim.x + threadIdx.x;
    if (t < SZ_ROIS) out[OFF_ROIS + t] = 0.f;
    else if (t < SZ_ROIS + SZ_RIDX) {
        int i = t - SZ_ROIS;
        out[OFF_RIDX + i] = (float)(i / POST_NMS);
    }
}

// =================================================================
// sequential greedy NMS scan (1 warp per image), write kept rois
// =================================================================
__global__ void scan_kernel(float* __restrict__ out)
{
    const int img  = blockIdx.x;
    const int lane = threadIdx.x;

    unsigned sup0, sup1, sup2;
    {
        unsigned v[3];
#pragma unroll
        for (int s = 0; s < 3; s++) {
            unsigned vv = 0;
            int w = s*32 + lane;
            for (int b = 0; b < 32; b++) {
                int i = w*32 + b;
                if (i < PRE_NMS && g_scores_top[(size_t)img*PRE_NMS + i] == -INFINITY)
                    vv |= 1u << b;
            }
            v[s] = vv;
        }
        sup0 = v[0]; sup1 = v[1]; sup2 = v[2];
    }

    int keep = 0;
    const unsigned* maskbase = g_mask + (size_t)img*PRE_NMS*NMS_WORDS;

    for (int i = 0; i < PRE_NMS; i++) {
        int w = i >> 5, b = i & 31;
        int slot = w >> 5, owner = w & 31;
        unsigned myw = (slot == 0) ? sup0 : (slot == 1 ? sup1 : sup2);
        unsigned word = __shfl_sync(0xFFFFFFFFu, myw, owner);
        if (!((word >> b) & 1u)) {
            if (keep < POST_NMS && lane == 0) {
                float4 bx = g_boxes_top[(size_t)img*PRE_NMS + i];
                float* o = out + OFF_ROIS + ((size_t)img*POST_NMS + keep)*4;
                o[0] = bx.x; o[1] = bx.y; o[2] = bx.z; o[3] = bx.w;
            }
            keep++;
            const unsigned* mrow = maskbase + (size_t)i * NMS_WORDS;
            int w0i = lane, w1i = 32 + lane, w2i = 64 + lane;
            if (w0i < NMS_WORDS) sup0 |= mrow[w0i];
            if (w1i < NMS_WORDS) sup1 |= mrow[w1i];
            if (w2i < NMS_WORDS) sup2 |= mrow[w2i];
        }
    }
}

// =================================================================
// launch
// =================================================================
extern "C" void kernel_launch(void* const* d_in, const int* in_sizes, int n_in,
                              void* d_out, int out_size)
{
    const float* x   = (const float*)d_in[0];
    const void*  ih  = d_in[1];
    const void*  iw  = d_in[2];
    const float* W1  = (const float*)d_in[3];
    const float* b1  = (const float*)d_in[4];
    const float* Ws  = (const float*)d_in[5];
    const float* bs  = (const float*)d_in[6];
    const float* Wl  = (const float*)d_in[7];
    const float* bl  = (const float*)d_in[8];
    float* out = (float*)d_out;

    static int smem_set = 0;
    if (!smem_set) {
        cudaFuncSetAttribute(conv_hmma_kernel,
                             cudaFuncAttributeMaxDynamicSharedMemorySize,
                             SM_CONV_TOTAL);
        smem_set = 1;
    }

    // weight split/pre-swizzle (x64 scale)
    wprep_kernel<<<(4*NCHUNK*128*32 + 255)/256, 256>>>(W1);
    // HMMA split-fp16 3x3 conv + relu
    conv_hmma_kernel<<<dim3(4, 32, N_IMG), 256, SM_CONV_TOTAL>>>(x, b1);
    // 1x1 heads -> d_out locs/scores
    conv1x1_kernel<<<dim3(NPOS/128, N_IMG), 128>>>(Wl, bl, Ws, bs, out);
    // anchors -> d_out anchor region
    anchor_kernel<<<(A_TOT + 255)/256, 256>>>(out);
    // zero rois + roi indices
    fill_kernel<<<(SZ_ROIS + SZ_RIDX + 255)/256, 256>>>(out);
    // proposals + sort keys
    proposal_kernel<<<(N_IMG*SORT_N)/256, 256>>>(out, ih, iw);

    // bitonic sort (descending score, ascending index ties)
    bitonic_local<<<128, 1024>>>(0, 1);
    for (int k = 4096; k <= SORT_N; k <<= 1) {
        for (int j = k >> 1; j >= CHUNK; j >>= 1)
            bitonic_global_step<<<(N_IMG*SORT_N/2)/256, 256>>>(k, j);
        bitonic_local<<<128, 1024>>>(k, 0);
    }

    // top-3000 gather
    gather_kernel<<<(N_IMG*PRE_NMS + 255)/256, 256>>>();
    // IoU bitmask
    mask_kernel<<<dim3(47, 47, N_IMG), 64>>>();
    // sequential NMS scan -> rois
    scan_kernel<<<N_IMG, 32>>>(out);
}

// round 8
// speedup vs baseline: 1.8463x; 1.1162x over previous
#include <cuda_runtime.h>
#include <cuda_fp16.h>
#include <math.h>
#include <stdint.h>

// ---------------- problem constants ----------------
#define N_IMG 4
#define CIN   512
#define HH    64
#define WW    64
#define NPOS  (HH*WW)            // 4096
#define NANCH 9
#define A_TOT (NPOS*NANCH)       // 36864
#define SORT_N 65536
#define PRE_NMS  3000
#define POST_NMS 300
#define NMS_WORDS 94             // ceil(3000/32)
#define NMS_THRESH 0.7f
#define MIN_SIZE 16.0f

// ---------------- d_out layout (floats), reference return order ----------------
#define SZ_LOCS   (N_IMG*A_TOT*4)            // 589824
#define OFF_LOCS  0
#define SZ_SCORES (N_IMG*A_TOT*2)            // 294912
#define OFF_SCORES (OFF_LOCS+SZ_LOCS)        // 589824
#define SZ_ROIS   (N_IMG*POST_NMS*4)         // 4800
#define OFF_ROIS  (OFF_SCORES+SZ_SCORES)     // 884736
#define SZ_RIDX   (N_IMG*POST_NMS)           // 1200
#define OFF_RIDX  (OFF_ROIS+SZ_ROIS)         // 889536
#define OFF_ANCHOR (OFF_RIDX+SZ_RIDX)        // 890736  (size 147456)

// ---------------- device scratch ----------------
__device__ float               g_hidden[N_IMG*CIN*NPOS];        // 33.5 MB
__device__ float4              g_rois_all[N_IMG*A_TOT];         // 2.36 MB
__device__ unsigned long long  g_keys[N_IMG*SORT_N];            // 2 MB
__device__ float4              g_boxes_top[N_IMG*PRE_NMS];      // 192 KB
__device__ float               g_scores_top[N_IMG*PRE_NMS];     // 48 KB
__device__ unsigned            g_mask[(size_t)N_IMG*PRE_NMS*NMS_WORDS]; // 4.5 MB

// split-fp16 weights (scaled x64), pre-swizzled smem-tile layout:
// [ot(4)][ch(72)] tiles of 16KB ([128 oc rows x 64 f16 = 128B], SW128 swizzled)
#define NCHUNK 72
__device__ uint4 g_wt_hi[4*NCHUNK*1024];   // 4.7 MB
__device__ uint4 g_wt_lo[4*NCHUNK*1024];   // 4.7 MB

// split-fp16 transposed features: [img][pos][cin] fp16
__device__ __half g_xt_hi[(size_t)N_IMG*NPOS*CIN];   // 16.8 MB
__device__ __half g_xt_lo[(size_t)N_IMG*NPOS*CIN];   // 16.8 MB

#define W_SCALE 64.0f
#define W_INV   (1.0f/64.0f)

#define SWZ128(o) ((o) ^ (((o) >> 3) & 0x70))

__device__ __forceinline__ unsigned smem_u32(const void* p) {
    unsigned a;
    asm("{ .reg .u64 t; cvta.to.shared.u64 t, %1; cvt.u32.u64 %0, t; }"
        : "=r"(a) : "l"(p));
    return a;
}

__device__ __forceinline__ void cp_async16(unsigned dst, const void* src, unsigned src_sz)
{
    asm volatile("cp.async.cg.shared.global [%0], [%1], 16, %2;"
                 :: "r"(dst), "l"(src), "r"(src_sz) : "memory");
}
#define CP_COMMIT() asm volatile("cp.async.commit_group;" ::: "memory")
#define CP_WAIT(n)  asm volatile("cp.async.wait_group %0;" :: "n"(n) : "memory")

__device__ __forceinline__ void ldsm4(unsigned& r0, unsigned& r1,
                                      unsigned& r2, unsigned& r3, unsigned addr)
{
    asm volatile("ldmatrix.sync.aligned.m8n8.x4.shared.b16 {%0,%1,%2,%3}, [%4];"
                 : "=r"(r0), "=r"(r1), "=r"(r2), "=r"(r3) : "r"(addr));
}

__device__ __forceinline__ void mma16816(float* c, const unsigned* a, const unsigned* b)
{
    asm volatile(
        "mma.sync.aligned.m16n8k16.row.col.f32.f16.f16.f32 "
        "{%0,%1,%2,%3}, {%4,%5,%6,%7}, {%8,%9}, {%0,%1,%2,%3};"
        : "+f"(c[0]), "+f"(c[1]), "+f"(c[2]), "+f"(c[3])
        : "r"(a[0]), "r"(a[1]), "r"(a[2]), "r"(a[3]), "r"(b[0]), "r"(b[1]));
}

// =================================================================
// weight prep: fp32 W1 [oc][cin][3][3] -> x64-scaled split fp16 hi/lo
// tiles, pre-swizzled. chunk ch = kk*8 + ccb (tap kk, cin block ccb*64)
// =================================================================
__global__ void wprep_kernel(const float* __restrict__ W1)
{
    int t = blockIdx.x * blockDim.x + threadIdx.x;
    if (t >= 4*NCHUNK*128*32) return;
    int c2 = t & 31;             // column pair
    int r  = (t >> 5) & 127;     // oc row in tile
    int tc = t >> 12;            // ot*72 + ch
    int ch = tc % NCHUNK;
    int ot = tc / NCHUNK;
    int kk  = ch >> 3;
    int ccb = ch & 7;
    int c  = c2 * 2;
    int cc = ccb*64 + c;
    int oc = ot*128 + r;

    float w0 = W1[(size_t)oc*4608 + (size_t)cc*9 + kk] * W_SCALE;
    float w1 = W1[(size_t)oc*4608 + (size_t)(cc+1)*9 + kk] * W_SCALE;
    __half h0 = __float2half_rn(w0), h1 = __float2half_rn(w1);
    __half l0 = __float2half_rn(w0 - __half2float(h0));
    __half l1 = __float2half_rn(w1 - __half2float(h1));

    unsigned off = (unsigned)(r*128 + c*2);
    off = SWZ128(off);
    size_t base = (size_t)tc * 16384;
    *reinterpret_cast<__half2*>(reinterpret_cast<char*>(g_wt_hi) + base + off) =
        __halves2half2(h0, h1);
    *reinterpret_cast<__half2*>(reinterpret_cast<char*>(g_wt_lo) + base + off) =
        __halves2half2(l0, l1);
}

// =================================================================
// x split + transpose: x [img][c][pos] fp32 -> xt_hi/lo [img][pos][c] fp16
// 32x32 tiles via smem
// =================================================================
__global__ void xsplit_kernel(const float* __restrict__ x)
{
    __shared__ float tile[32][33];
    const int p0  = blockIdx.x * 32;
    const int c0  = blockIdx.y * 32;
    const int img = blockIdx.z;
    const int tx = threadIdx.x, ty = threadIdx.y;   // 32 x 8

#pragma unroll
    for (int i = 0; i < 4; i++) {
        int c = c0 + ty + i*8;
        tile[ty + i*8][tx] = x[((size_t)img*CIN + c)*NPOS + p0 + tx];
    }
    __syncthreads();

#pragma unroll
    for (int i = 0; i < 4; i++) {
        int p = p0 + ty + i*8;
        float v = tile[tx][ty + i*8];
        __half h = __float2half_rn(v);
        __half l = __float2half_rn(v - __half2float(h));
        size_t o = ((size_t)img*NPOS + p)*CIN + c0 + tx;
        g_xt_hi[o] = h;
        g_xt_lo[o] = l;
    }
}

// =================================================================
// HMMA split-fp16 conv, cp.async double-buffered.
// per CTA 128 oc x 128 pos (2 image rows), 72 chunks (tap x 64 cin).
// 3 mma per tile-step: wh*xh + wh*xl + wl*xh, one fp32 acc, /64 at end.
// =================================================================
#define BUF_STRIDE 65536
#define SM_AHI 0
#define SM_ALO 16384
#define SM_BHI 32768
#define SM_BLO 49152
#define SM_CONV_TOTAL (2*BUF_STRIDE)     // 131072

__global__ void __launch_bounds__(256) conv_hmma_kernel(const float* __restrict__ b1)
{
    extern __shared__ char smem[];
    const unsigned sbase = smem_u32(smem);
    const int tid  = threadIdx.x;
    const int wid  = tid >> 5;
    const int lane = tid & 31;
    const int ot   = blockIdx.x;          // oc tile 0..3
    const int pt   = blockIdx.y;          // pos tile 0..31
    const int img  = blockIdx.z;

    const int wm = wid >> 2;              // 0..1 : oc block of 64
    const int wn = wid & 3;               // 0..3 : pos block of 32

    const int sel = lane >> 3;            // ldmatrix matrix select 0..3
    const int l7  = lane & 7;

    const int pos0 = pt * 128;
    const int y0   = pos0 >> 6;           // 2*pt
    // B-issue mapping: thread = (pos 0..127, half 0..1)
    const int bp   = tid & 127;
    const int bh_  = tid >> 7;
    const int rowN = bp >> 6;
    const int colN = bp & 63;

    float acc[4][4][4];
#pragma unroll
    for (int mt = 0; mt < 4; mt++)
#pragma unroll
        for (int nt = 0; nt < 4; nt++)
#pragma unroll
            for (int k = 0; k < 4; k++) acc[mt][nt][k] = 0.f;

    const unsigned a_row  = (unsigned)(wm*64 + (sel & 1)*8 + l7);
    const unsigned a_colb = (unsigned)((sel >> 1) * 16);
    const unsigned b_row  = (unsigned)(wn*32 + (sel >> 1)*8 + l7);
    const unsigned b_colb = (unsigned)((sel & 1) * 16);

    const __half* xh_img = g_xt_hi + (size_t)img*NPOS*CIN;
    const __half* xl_img = g_xt_lo + (size_t)img*NPOS*CIN;

    // ---- async load issue for one chunk into buffer buf ----
    auto issue_chunk = [&](int ch, int buf) {
        const unsigned bb = sbase + buf*BUF_STRIDE;
        // A: 1024 x 16B each of hi/lo, linear pre-swizzled
        {
            const uint4* sh = g_wt_hi + (size_t)(ot*NCHUNK + ch) * 1024;
            const uint4* sl = g_wt_lo + (size_t)(ot*NCHUNK + ch) * 1024;
#pragma unroll
            for (int i = 0; i < 4; i++) {
                cp_async16(bb + SM_AHI + (tid + i*256)*16, sh + tid + i*256, 16u);
                cp_async16(bb + SM_ALO + (tid + i*256)*16, sl + tid + i*256, 16u);
            }
        }
        // B: per (pos, half): 4 x 16B from xt_hi + 4 x 16B from xt_lo
        {
            const int kk  = ch >> 3;
            const int ccb = ch & 7;
            const int dy  = kk / 3 - 1;
            const int dx  = kk % 3 - 1;
            const int gy  = y0 + rowN + dy;
            const int gx  = colN + dx;
            const bool valid = (gy >= 0) && (gy < HH) && (gx >= 0) && (gx < WW);
            const unsigned sz = valid ? 16u : 0u;
            const size_t srcoff = ((size_t)(gy*WW + gx))*CIN + ccb*64 + bh_*32;
            const __half* srch = xh_img + srcoff;
            const __half* srcl = xl_img + srcoff;
#pragma unroll
            for (int k = 0; k < 4; k++) {
                unsigned d = SWZ128((unsigned)(bp*128 + bh_*64 + k*16));
                cp_async16(bb + SM_BHI + d, srch + k*8, sz);
                cp_async16(bb + SM_BLO + d, srcl + k*8, sz);
            }
        }
        CP_COMMIT();
    };

    issue_chunk(0, 0);

    for (int ch = 0; ch < NCHUNK; ch++) {
        if (ch + 1 < NCHUNK) {
            issue_chunk(ch + 1, (ch + 1) & 1);
            CP_WAIT(1);
        } else {
            CP_WAIT(0);
        }
        __syncthreads();

        const unsigned bb = sbase + (ch & 1)*BUF_STRIDE;
#pragma unroll
        for (int ks = 0; ks < 4; ks++) {
            const unsigned kcol = (unsigned)(ks * 32);
            unsigned bh[8], bl[8];
            {
                unsigned off0 = SWZ128(b_row*128 + kcol + b_colb);
                unsigned off1 = SWZ128((b_row+16)*128 + kcol + b_colb);
                ldsm4(bh[0], bh[1], bh[2], bh[3], bb + SM_BHI + off0);
                ldsm4(bh[4], bh[5], bh[6], bh[7], bb + SM_BHI + off1);
                ldsm4(bl[0], bl[1], bl[2], bl[3], bb + SM_BLO + off0);
                ldsm4(bl[4], bl[5], bl[6], bl[7], bb + SM_BLO + off1);
            }
#pragma unroll
            for (int mt = 0; mt < 4; mt++) {
                unsigned aoff = SWZ128((a_row + mt*16)*128 + kcol + a_colb);
                unsigned ah[4], al[4];
                ldsm4(ah[0], ah[1], ah[2], ah[3], bb + SM_AHI + aoff);
                ldsm4(al[0], al[1], al[2], al[3], bb + SM_ALO + aoff);
#pragma unroll
                for (int nt = 0; nt < 4; nt++) {
                    mma16816(acc[mt][nt], ah, &bh[nt*2]);   // wh*xh
                    mma16816(acc[mt][nt], ah, &bl[nt*2]);   // wh*xl
                    mma16816(acc[mt][nt], al, &bh[nt*2]);   // wl*xh
                }
            }
        }
        __syncthreads();
    }

    // ---- epilogue: /64, +bias, relu, store ----
    const int mrow = lane >> 2;           // 0..7
    const int ncol = (lane & 3) * 2;      // 0,2,4,6
#pragma unroll
    for (int mt = 0; mt < 4; mt++) {
        const int ocA = ot*128 + wm*64 + mt*16 + mrow;
        const int ocB = ocA + 8;
        const float biasA = b1[ocA];
        const float biasB = b1[ocB];
#pragma unroll
        for (int nt = 0; nt < 4; nt++) {
            const int pos = pos0 + wn*32 + nt*8 + ncol;
            float v0 = acc[mt][nt][0] * W_INV + biasA;
            float v1 = acc[mt][nt][1] * W_INV + biasA;
            float v2 = acc[mt][nt][2] * W_INV + biasB;
            float v3 = acc[mt][nt][3] * W_INV + biasB;
            v0 = v0 > 0.f ? v0 : 0.f;
            v1 = v1 > 0.f ? v1 : 0.f;
            v2 = v2 > 0.f ? v2 : 0.f;
            v3 = v3 > 0.f ? v3 : 0.f;
            *reinterpret_cast<float2*>(
                g_hidden + ((size_t)img*CIN + ocA)*NPOS + pos) = make_float2(v0, v1);
            *reinterpret_cast<float2*>(
                g_hidden + ((size_t)img*CIN + ocB)*NPOS + pos) = make_float2(v2, v3);
        }
    }
}

// =================================================================
// 1x1 convs (loc 36 + score 18 = 54 outputs) written directly into
// d_out in the reference's reshaped layout.
// =================================================================
#define NOUT 54
__global__ __launch_bounds__(128) void conv1x1_kernel(
    const float* __restrict__ Wl, const float* __restrict__ bl,
    const float* __restrict__ Ws, const float* __restrict__ bs,
    float* __restrict__ out)
{
    __shared__ float Wc[64][NOUT];
    const int tid = threadIdx.x;
    const int img = blockIdx.y;
    const int pos = blockIdx.x * 128 + tid;

    float acc[NOUT];
#pragma unroll
    for (int o = 0; o < NOUT; o++) acc[o] = 0.f;

    const float* hid = g_hidden + (size_t)img * CIN * NPOS;

    for (int c0 = 0; c0 < CIN; c0 += 64) {
        for (int idx = tid; idx < 64*NOUT; idx += 128) {
            int c = idx / NOUT;
            int o = idx - c*NOUT;
            Wc[c][o] = (o < 36) ? Wl[(size_t)o*CIN + c0 + c]
                                : Ws[(size_t)(o-36)*CIN + c0 + c];
        }
        __syncthreads();
#pragma unroll 4
        for (int c = 0; c < 64; c++) {
            float h = hid[(size_t)(c0+c)*NPOS + pos];
#pragma unroll
            for (int o = 0; o < NOUT; o++) acc[o] += h * Wc[c][o];
        }
        __syncthreads();
    }

    float* locout = out + OFF_LOCS + (size_t)img*A_TOT*4 + (size_t)pos*36;
#pragma unroll
    for (int o = 0; o < 36; o++) locout[o] = acc[o] + bl[o];
    float* scout = out + OFF_SCORES + (size_t)img*A_TOT*2 + (size_t)pos*18;
#pragma unroll
    for (int o = 0; o < 18; o++) scout[o] = acc[36+o] + bs[o];
}

// =================================================================
// anchor generation into d_out anchor region
// =================================================================
__global__ void anchor_kernel(float* __restrict__ out)
{
    int i = blockIdx.x * blockDim.x + threadIdx.x;
    if (i >= A_TOT) return;
    int a   = i % 9;
    int pos = i / 9;
    int y = pos / WW, x = pos % WW;
    int ri = a / 3, si = a % 3;
    double rr = (ri == 0) ? 0.5 : (ri == 1 ? 1.0 : 2.0);
    double ss = (si == 0) ? 8.0 : (si == 1 ? 16.0 : 32.0);
    double h = 16.0 * ss * sqrt(rr);
    double w = 16.0 * ss * sqrt(1.0 / rr);
    float ymin = (float)(8.0 - h*0.5);
    float xmin = (float)(8.0 - w*0.5);
    float ymax = (float)(8.0 + h*0.5);
    float xmax = (float)(8.0 + w*0.5);
    float sy = (float)y * 16.0f, sx = (float)x * 16.0f;
    reinterpret_cast<float4*>(out + OFF_ANCHOR)[i] =
        make_float4(sy + ymin, sx + xmin, sy + ymax, sx + xmax);
}

// =================================================================
// proposal: loc2bbox + clip + min-size filter + fg softmax + sort key
// =================================================================
__device__ __forceinline__ float read_dim(const void* p)
{
    int v = *(const int*)p;
    if (v > 0 && v < (1 << 20)) return (float)v;   // plausibly int32
    return *(const float*)p;                        // else float bits
}

__global__ void proposal_kernel(const float* __restrict__ out,
                                const void* __restrict__ p_ih,
                                const void* __restrict__ p_iw)
{
    int t = blockIdx.x * blockDim.x + threadIdx.x;
    int img = t >> 16;          // / 65536
    int i   = t & (SORT_N - 1);
    if (img >= N_IMG) return;
    if (i >= A_TOT) { g_keys[t] = ~0ULL; return; }

    const float4 anc = reinterpret_cast<const float4*>(out + OFF_ANCHOR)[i];
    const float* loc = out + OFF_LOCS + (size_t)img*A_TOT*4 + (size_t)i*4;
    const float l0 = loc[0], l1 = loc[1], l2 = loc[2], l3 = loc[3];
    const float* sc = out + OFF_SCORES + (size_t)img*A_TOT*2 + (size_t)i*2;
    const float s0 = sc[0], s1 = sc[1];

    float h  = anc.z - anc.x, w = anc.w - anc.y;
    float cy = anc.x + 0.5f*h, cx = anc.y + 0.5f*w;
    float ncy = l0*h + cy, ncx = l1*w + cx;
    float nh  = expf(l2)*h,  nw  = expf(l3)*w;

    float fh = read_dim(p_ih), fw = read_dim(p_iw);
    float y1 = fminf(fmaxf(ncy - 0.5f*nh, 0.f), fh);
    float x1 = fminf(fmaxf(ncx - 0.5f*nw, 0.f), fw);
    float y2 = fminf(fmaxf(ncy + 0.5f*nh, 0.f), fh);
    float x2 = fminf(fmaxf(ncx + 0.5f*nw, 0.f), fw);

    bool ok = ((y2 - y1) >= MIN_SIZE) && ((x2 - x1) >= MIN_SIZE);

    float m  = fmaxf(s0, s1);
    float e0 = expf(s0 - m), e1 = expf(s1 - m);
    float fg = e1 / (e0 + e1);
    float score = ok ? fg : -INFINITY;

    g_rois_all[(size_t)img*A_TOT + i] = make_float4(y1, x1, y2, x2);

    unsigned u    = __float_as_uint(score);
    unsigned mkey = u ^ ((u >> 31) ? 0xFFFFFFFFu : 0x80000000u);   // ascending map
    unsigned dkey = ~mkey;                                          // descending
    g_keys[(size_t)img*SORT_N + i] = ((unsigned long long)dkey << 32) | (unsigned)i;
}

// =================================================================
// bitonic sort, 64-bit keys, 65536 elems per image, 4 images
// =================================================================
#define CHUNK 2048
__global__ __launch_bounds__(1024) void bitonic_local(int kstart, int fullsort)
{
    __shared__ unsigned long long sk[CHUNK];
    const int chunk = blockIdx.x;                       // 0..127
    unsigned long long* K = g_keys + (size_t)chunk * CHUNK;
    const int gbase = (chunk & 31) * CHUNK;             // index within image
    const int tid = threadIdx.x;

    sk[tid]        = K[tid];
    sk[tid + 1024] = K[tid + 1024];
    __syncthreads();

    if (fullsort) {
        for (int k = 2; k <= CHUNK; k <<= 1) {
            for (int j = k >> 1; j > 0; j >>= 1) {
                int i   = ((tid & ~(j - 1)) << 1) | (tid & (j - 1));
                int ixj = i | j;
                bool up = (((gbase + i) & k) == 0);
                unsigned long long a = sk[i], b = sk[ixj];
                if ((a > b) == up) { sk[i] = b; sk[ixj] = a; }
                __syncthreads();
            }
        }
    } else {
        const int k = kstart;
        for (int j = 1024; j > 0; j >>= 1) {
            int i   = ((tid & ~(j - 1)) << 1) | (tid & (j - 1));
            int ixj = i | j;
            bool up = (((gbase + i) & k) == 0);
            unsigned long long a = sk[i], b = sk[ixj];
            if ((a > b) == up) { sk[i] = b; sk[ixj] = a; }
            __syncthreads();
        }
    }
    K[tid]        = sk[tid];
    K[tid + 1024] = sk[tid + 1024];
}

__global__ void bitonic_global_step(int k, int j)
{
    int t   = blockIdx.x * blockDim.x + threadIdx.x;   // 4 * 32768
    int img = t >> 15;
    int tt  = t & 32767;
    int i   = ((tt & ~(j - 1)) << 1) | (tt & (j - 1));
    int ixj = i | j;
    unsigned long long* K = g_keys + (size_t)img * SORT_N;
    unsigned long long a = K[i], b = K[ixj];
    bool up = ((i & k) == 0);
    if ((a > b) == up) { K[i] = b; K[ixj] = a; }
}

// =================================================================
// gather top-3000 boxes + scores
// =================================================================
__global__ void gather_kernel()
{
    int t = blockIdx.x * blockDim.x + threadIdx.x;
    if (t >= N_IMG * PRE_NMS) return;
    int img = t / PRE_NMS;
    int i   = t - img * PRE_NMS;
    unsigned long long key = g_keys[(size_t)img*SORT_N + i];
    unsigned idx = (unsigned)(key & 0xFFFFFFFFu);
    g_boxes_top[t] = g_rois_all[(size_t)img*A_TOT + idx];
    unsigned dkey = (unsigned)(key >> 32);
    unsigned mkey = ~dkey;
    unsigned u = (mkey & 0x80000000u) ? (mkey ^ 0x80000000u) : ~mkey;
    g_scores_top[t] = __uint_as_float(u);
}

// =================================================================
// NMS suppression bitmask (3000 x 3000, only j > i bits)
// =================================================================
__global__ __launch_bounds__(64) void mask_kernel()
{
    const int img  = blockIdx.z;
    const int rowb = blockIdx.y * 64;
    const int colb = blockIdx.x * 64;
    __shared__ float4 cb[64];
    const int t = threadIdx.x;
    int col0 = colb + t;
    cb[t] = (col0 < PRE_NMS) ? g_boxes_top[(size_t)img*PRE_NMS + col0]
                             : make_float4(0.f, 0.f, 0.f, 0.f);
    __syncthreads();

    int row = rowb + t;
    if (row >= PRE_NMS) return;
    float4 rb = g_boxes_top[(size_t)img*PRE_NMS + row];
    float ra = fmaxf(rb.z - rb.x, 0.f) * fmaxf(rb.w - rb.y, 0.f);

    unsigned w0 = 0, w1 = 0;
#pragma unroll 4
    for (int c = 0; c < 64; c++) {
        int col = colb + c;
        if (col >= PRE_NMS || col <= row) continue;
        float4 b = cb[c];
        float yy1 = fmaxf(rb.x, b.x), xx1 = fmaxf(rb.y, b.y);
        float yy2 = fminf(rb.z, b.z), xx2 = fminf(rb.w, b.w);
        float inter = fmaxf(yy2 - yy1, 0.f) * fmaxf(xx2 - xx1, 0.f);
        float ba = fmaxf(b.z - b.x, 0.f) * fmaxf(b.w - b.y, 0.f);
        float iou = inter / (ra + ba - inter + 1e-9f);
        if (iou > NMS_THRESH) {
            if (c < 32) w0 |= 1u << c; else w1 |= 1u << (c - 32);
        }
    }
    unsigned* mrow = g_mask + ((size_t)img*PRE_NMS + row) * NMS_WORDS;
    int wi = colb >> 5;
    mrow[wi] = w0;
    if (wi + 1 < NMS_WORDS) mrow[wi + 1] = w1;
}

// =================================================================
// zero rois region + write roi_indices
// =================================================================
__global__ void fill_kernel(float* __restrict__ out)
{
    int t = blockIdx.x * blockDim.x + threadIdx.x;
    if (t < SZ_ROIS) out[OFF_ROIS + t] = 0.f;
    else if (t < SZ_ROIS + SZ_RIDX) {
        int i = t - SZ_ROIS;
        out[OFF_RIDX + i] = (float)(i / POST_NMS);
    }
}

// =================================================================
// sequential greedy NMS scan (1 warp per image), write kept rois
// =================================================================
__global__ void scan_kernel(float* __restrict__ out)
{
    const int img  = blockIdx.x;
    const int lane = threadIdx.x;

    unsigned sup0, sup1, sup2;
    {
        unsigned v[3];
#pragma unroll
        for (int s = 0; s < 3; s++) {
            unsigned vv = 0;
            int w = s*32 + lane;
            for (int b = 0; b < 32; b++) {
                int i = w*32 + b;
                if (i < PRE_NMS && g_scores_top[(size_t)img*PRE_NMS + i] == -INFINITY)
                    vv |= 1u << b;
            }
            v[s] = vv;
        }
        sup0 = v[0]; sup1 = v[1]; sup2 = v[2];
    }

    int keep = 0;
    const unsigned* maskbase = g_mask + (size_t)img*PRE_NMS*NMS_WORDS;

    for (int i = 0; i < PRE_NMS; i++) {
        int w = i >> 5, b = i & 31;
        int slot = w >> 5, owner = w & 31;
        unsigned myw = (slot == 0) ? sup0 : (slot == 1 ? sup1 : sup2);
        unsigned word = __shfl_sync(0xFFFFFFFFu, myw, owner);
        if (!((word >> b) & 1u)) {
            if (keep < POST_NMS && lane == 0) {
                float4 bx = g_boxes_top[(size_t)img*PRE_NMS + i];
                float* o = out + OFF_ROIS + ((size_t)img*POST_NMS + keep)*4;
                o[0] = bx.x; o[1] = bx.y; o[2] = bx.z; o[3] = bx.w;
            }
            keep++;
            const unsigned* mrow = maskbase + (size_t)i * NMS_WORDS;
            int w0i = lane, w1i = 32 + lane, w2i = 64 + lane;
            if (w0i < NMS_WORDS) sup0 |= mrow[w0i];
            if (w1i < NMS_WORDS) sup1 |= mrow[w1i];
            if (w2i < NMS_WORDS) sup2 |= mrow[w2i];
        }
    }
}

// =================================================================
// launch
// =================================================================
extern "C" void kernel_launch(void* const* d_in, const int* in_sizes, int n_in,
                              void* d_out, int out_size)
{
    const float* x   = (const float*)d_in[0];
    const void*  ih  = d_in[1];
    const void*  iw  = d_in[2];
    const float* W1  = (const float*)d_in[3];
    const float* b1  = (const float*)d_in[4];
    const float* Ws  = (const float*)d_in[5];
    const float* bs  = (const float*)d_in[6];
    const float* Wl  = (const float*)d_in[7];
    const float* bl  = (const float*)d_in[8];
    float* out = (float*)d_out;

    static int smem_set = 0;
    if (!smem_set) {
        cudaFuncSetAttribute(conv_hmma_kernel,
                             cudaFuncAttributeMaxDynamicSharedMemorySize,
                             SM_CONV_TOTAL);
        smem_set = 1;
    }

    // weight split/pre-swizzle (x64 scale)
    wprep_kernel<<<(4*NCHUNK*128*32 + 255)/256, 256>>>(W1);
    // x split + transpose to fp16 hi/lo
    xsplit_kernel<<<dim3(NPOS/32, CIN/32, N_IMG), dim3(32, 8)>>>(x);
    // HMMA split-fp16 3x3 conv + relu (cp.async double-buffered)
    conv_hmma_kernel<<<dim3(4, 32, N_IMG), 256, SM_CONV_TOTAL>>>(b1);
    // 1x1 heads -> d_out locs/scores
    conv1x1_kernel<<<dim3(NPOS/128, N_IMG), 128>>>(Wl, bl, Ws, bs, out);
    // anchors -> d_out anchor region
    anchor_kernel<<<(A_TOT + 255)/256, 256>>>(out);
    // zero rois + roi indices
    fill_kernel<<<(SZ_ROIS + SZ_RIDX + 255)/256, 256>>>(out);
    // proposals + sort keys
    proposal_kernel<<<(N_IMG*SORT_N)/256, 256>>>(out, ih, iw);

    // bitonic sort (descending score, ascending index ties)
    bitonic_local<<<128, 1024>>>(0, 1);
    for (int k = 4096; k <= SORT_N; k <<= 1) {
        for (int j = k >> 1; j >= CHUNK; j >>= 1)
            bitonic_global_step<<<(N_IMG*SORT_N/2)/256, 256>>>(k, j);
        bitonic_local<<<128, 1024>>>(k, 0);
    }

    // top-3000 gather
    gather_kernel<<<(N_IMG*PRE_NMS + 255)/256, 256>>>();
    // IoU bitmask
    mask_kernel<<<dim3(47, 47, N_IMG), 64>>>();
    // sequential NMS scan -> rois
    scan_kernel<<<N_IMG, 32>>>(out);
}

// round 10
// speedup vs baseline: 1.9009x; 1.0296x over previous
#include <cuda_runtime.h>
#include <cuda_fp16.h>
#include <math.h>
#include <stdint.h>

// ---------------- problem constants ----------------
#define N_IMG 4
#define CIN   512
#define HH    64
#define WW    64
#define NPOS  (HH*WW)            // 4096
#define NANCH 9
#define A_TOT (NPOS*NANCH)       // 36864
#define SORT_N 65536
#define PRE_NMS  3000
#define POST_NMS 300
#define NMS_WORDS 94             // ceil(3000/32)
#define NMS_THRESH 0.7f
#define MIN_SIZE 16.0f

// ---------------- d_out layout (floats), reference return order ----------------
#define SZ_LOCS   (N_IMG*A_TOT*4)            // 589824
#define OFF_LOCS  0
#define SZ_SCORES (N_IMG*A_TOT*2)            // 294912
#define OFF_SCORES (OFF_LOCS+SZ_LOCS)        // 589824
#define SZ_ROIS   (N_IMG*POST_NMS*4)         // 4800
#define OFF_ROIS  (OFF_SCORES+SZ_SCORES)     // 884736
#define SZ_RIDX   (N_IMG*POST_NMS)           // 1200
#define OFF_RIDX  (OFF_ROIS+SZ_ROIS)         // 889536
#define OFF_ANCHOR (OFF_RIDX+SZ_RIDX)        // 890736  (size 147456)

// ---------------- device scratch ----------------
__device__ float               g_hidden[N_IMG*CIN*NPOS];        // 33.5 MB
__device__ float4              g_rois_all[N_IMG*A_TOT];         // 2.36 MB
__device__ unsigned long long  g_keys[N_IMG*SORT_N];            // 2 MB
__device__ float4              g_boxes_top[N_IMG*PRE_NMS];      // 192 KB
__device__ float               g_scores_top[N_IMG*PRE_NMS];     // 48 KB
__device__ unsigned            g_mask[(size_t)N_IMG*PRE_NMS*NMS_WORDS]; // 4.5 MB

// split-fp16 weights (scaled x64), pre-swizzled smem-tile layout:
// [ot(4)][ch(72)] tiles of 16KB ([128 oc rows x 64 f16 = 128B], SW128 swizzled)
#define NCHUNK 72
__device__ uint4 g_wt_hi[4*NCHUNK*1024];   // 4.7 MB
__device__ uint4 g_wt_lo[4*NCHUNK*1024];   // 4.7 MB

// split-fp16 transposed features: [img][pos][cin] fp16
__device__ __half g_xt_hi[(size_t)N_IMG*NPOS*CIN];   // 16.8 MB
__device__ __half g_xt_lo[(size_t)N_IMG*NPOS*CIN];   // 16.8 MB

#define NOUT 54

#define W_SCALE 64.0f
#define W_INV   (1.0f/64.0f)

#define SWZ128(o) ((o) ^ (((o) >> 3) & 0x70))

__device__ __forceinline__ unsigned smem_u32(const void* p) {
    unsigned a;
    asm("{ .reg .u64 t; cvta.to.shared.u64 t, %1; cvt.u32.u64 %0, t; }"
        : "=r"(a) : "l"(p));
    return a;
}

__device__ __forceinline__ void cp_async16(unsigned dst, const void* src, unsigned src_sz)
{
    asm volatile("cp.async.cg.shared.global [%0], [%1], 16, %2;"
                 :: "r"(dst), "l"(src), "r"(src_sz) : "memory");
}
#define CP_COMMIT() asm volatile("cp.async.commit_group;" ::: "memory")
#define CP_WAIT(n)  asm volatile("cp.async.wait_group %0;" :: "n"(n) : "memory")

__device__ __forceinline__ void ldsm4(unsigned& r0, unsigned& r1,
                                      unsigned& r2, unsigned& r3, unsigned addr)
{
    asm volatile("ldmatrix.sync.aligned.m8n8.x4.shared.b16 {%0,%1,%2,%3}, [%4];"
                 : "=r"(r0), "=r"(r1), "=r"(r2), "=r"(r3) : "r"(addr));
}

__device__ __forceinline__ void mma16816(float* c, const unsigned* a, const unsigned* b)
{
    asm volatile(
        "mma.sync.aligned.m16n8k16.row.col.f32.f16.f16.f32 "
        "{%0,%1,%2,%3}, {%4,%5,%6,%7}, {%8,%9}, {%0,%1,%2,%3};"
        : "+f"(c[0]), "+f"(c[1]), "+f"(c[2]), "+f"(c[3])
        : "r"(a[0]), "r"(a[1]), "r"(a[2]), "r"(a[3]), "r"(b[0]), "r"(b[1]));
}

// =================================================================
// weight prep: fp32 W1 [oc][cin][3][3] -> x64-scaled split fp16 hi/lo
// tiles, pre-swizzled. chunk ch = kk*8 + ccb (tap kk, cin block ccb*64)
// =================================================================
__global__ void wprep_kernel(const float* __restrict__ W1)
{
    int t = blockIdx.x * blockDim.x + threadIdx.x;
    if (t >= 4*NCHUNK*128*32) return;
    int c2 = t & 31;             // column pair
    int r  = (t >> 5) & 127;     // oc row in tile
    int tc = t >> 12;            // ot*72 + ch
    int ch = tc % NCHUNK;
    int ot = tc / NCHUNK;
    int kk  = ch >> 3;
    int ccb = ch & 7;
    int c  = c2 * 2;
    int cc = ccb*64 + c;
    int oc = ot*128 + r;

    float w0 = W1[(size_t)oc*4608 + (size_t)cc*9 + kk] * W_SCALE;
    float w1 = W1[(size_t)oc*4608 + (size_t)(cc+1)*9 + kk] * W_SCALE;
    __half h0 = __float2half_rn(w0), h1 = __float2half_rn(w1);
    __half l0 = __float2half_rn(w0 - __half2float(h0));
    __half l1 = __float2half_rn(w1 - __half2float(h1));

    unsigned off = (unsigned)(r*128 + c*2);
    off = SWZ128(off);
    size_t base = (size_t)tc * 16384;
    *reinterpret_cast<__half2*>(reinterpret_cast<char*>(g_wt_hi) + base + off) =
        __halves2half2(h0, h1);
    *reinterpret_cast<__half2*>(reinterpret_cast<char*>(g_wt_lo) + base + off) =
        __halves2half2(l0, l1);
}

// =================================================================
// x split + transpose: x [img][c][pos] fp32 -> xt_hi/lo [img][pos][c] fp16
// =================================================================
__global__ void xsplit_kernel(const float* __restrict__ x)
{
    __shared__ float tile[32][33];
    const int p0  = blockIdx.x * 32;
    const int c0  = blockIdx.y * 32;
    const int img = blockIdx.z;
    const int tx = threadIdx.x, ty = threadIdx.y;   // 32 x 8

#pragma unroll
    for (int i = 0; i < 4; i++) {
        int c = c0 + ty + i*8;
        tile[ty + i*8][tx] = x[((size_t)img*CIN + c)*NPOS + p0 + tx];
    }
    __syncthreads();

#pragma unroll
    for (int i = 0; i < 4; i++) {
        int p = p0 + ty + i*8;
        float v = tile[tx][ty + i*8];
        __half h = __float2half_rn(v);
        __half l = __float2half_rn(v - __half2float(h));
        size_t o = ((size_t)img*NPOS + p)*CIN + c0 + tx;
        g_xt_hi[o] = h;
        g_xt_lo[o] = l;
    }
}

// =================================================================
// HMMA split-fp16 conv, 3-stage cp.async ring, one barrier per chunk.
// per CTA 128 oc x 128 pos (2 image rows), 72 chunks (tap x 64 cin).
// 3 mma per tile-step: wh*xh + wh*xl + wl*xh, one fp32 acc, /64 at end.
// =================================================================
#define BUF_STRIDE 65536
#define NSTAGE 3
#define SM_AHI 0
#define SM_ALO 16384
#define SM_BHI 32768
#define SM_BLO 49152
#define SM_CONV_TOTAL (NSTAGE*BUF_STRIDE)     // 196608

__global__ void __launch_bounds__(256) conv_hmma_kernel(const float* __restrict__ b1)
{
    extern __shared__ char smem[];
    const unsigned sbase = smem_u32(smem);
    const int tid  = threadIdx.x;
    const int wid  = tid >> 5;
    const int lane = tid & 31;
    const int ot   = blockIdx.x;          // oc tile 0..3
    const int pt   = blockIdx.y;          // pos tile 0..31
    const int img  = blockIdx.z;

    const int wm = wid >> 2;              // 0..1 : oc block of 64
    const int wn = wid & 3;               // 0..3 : pos block of 32

    const int sel = lane >> 3;            // ldmatrix matrix select 0..3
    const int l7  = lane & 7;

    const int pos0 = pt * 128;
    const int y0   = pos0 >> 6;           // 2*pt
    const int bp   = tid & 127;           // B-issue pos
    const int bh_  = tid >> 7;            // B-issue k half
    const int rowN = bp >> 6;
    const int colN = bp & 63;

    float acc[4][4][4];
#pragma unroll
    for (int mt = 0; mt < 4; mt++)
#pragma unroll
        for (int nt = 0; nt < 4; nt++)
#pragma unroll
            for (int k = 0; k < 4; k++) acc[mt][nt][k] = 0.f;

    const unsigned a_row  = (unsigned)(wm*64 + (sel & 1)*8 + l7);
    const unsigned a_colb = (unsigned)((sel >> 1) * 16);
    const unsigned b_row  = (unsigned)(wn*32 + (sel >> 1)*8 + l7);
    const unsigned b_colb = (unsigned)((sel & 1) * 16);

    const __half* xh_img = g_xt_hi + (size_t)img*NPOS*CIN;
    const __half* xl_img = g_xt_lo + (size_t)img*NPOS*CIN;

    auto issue_chunk = [&](int ch) {
        const unsigned bb = sbase + (unsigned)(ch % NSTAGE)*BUF_STRIDE;
        {
            const uint4* sh = g_wt_hi + (size_t)(ot*NCHUNK + ch) * 1024;
            const uint4* sl = g_wt_lo + (size_t)(ot*NCHUNK + ch) * 1024;
#pragma unroll
            for (int i = 0; i < 4; i++) {
                cp_async16(bb + SM_AHI + (tid + i*256)*16, sh + tid + i*256, 16u);
                cp_async16(bb + SM_ALO + (tid + i*256)*16, sl + tid + i*256, 16u);
            }
        }
        {
            const int kk  = ch >> 3;
            const int ccb = ch & 7;
            const int dy  = kk / 3 - 1;
            const int dx  = kk % 3 - 1;
            const int gy  = y0 + rowN + dy;
            const int gx  = colN + dx;
            const bool valid = (gy >= 0) && (gy < HH) && (gx >= 0) && (gx < WW);
            const unsigned sz = valid ? 16u : 0u;
            const size_t srcoff = ((size_t)(gy*WW + gx))*CIN + ccb*64 + bh_*32;
            const __half* srch = xh_img + srcoff;
            const __half* srcl = xl_img + srcoff;
#pragma unroll
            for (int k = 0; k < 4; k++) {
                unsigned d = SWZ128((unsigned)(bp*128 + bh_*64 + k*16));
                cp_async16(bb + SM_BHI + d, srch + k*8, sz);
                cp_async16(bb + SM_BLO + d, srcl + k*8, sz);
            }
        }
        CP_COMMIT();
    };

    issue_chunk(0);
    issue_chunk(1);

    for (int ch = 0; ch < NCHUNK; ch++) {
        CP_WAIT(1);                 // guarantees group ch complete (2 in flight max)
        __syncthreads();            // cross-thread visibility; also protects ring reuse
        if (ch + 2 < NCHUNK) issue_chunk(ch + 2);
        else CP_COMMIT();           // empty group keeps wait_group accounting uniform

        const unsigned bb = sbase + (unsigned)(ch % NSTAGE)*BUF_STRIDE;
#pragma unroll
        for (int ks = 0; ks < 4; ks++) {
            const unsigned kcol = (unsigned)(ks * 32);
            unsigned bh[8], bl[8];
            {
                unsigned off0 = SWZ128(b_row*128 + kcol + b_colb);
                unsigned off1 = SWZ128((b_row+16)*128 + kcol + b_colb);
                ldsm4(bh[0], bh[1], bh[2], bh[3], bb + SM_BHI + off0);
                ldsm4(bh[4], bh[5], bh[6], bh[7], bb + SM_BHI + off1);
                ldsm4(bl[0], bl[1], bl[2], bl[3], bb + SM_BLO + off0);
                ldsm4(bl[4], bl[5], bl[6], bl[7], bb + SM_BLO + off1);
            }
#pragma unroll
            for (int mt = 0; mt < 4; mt++) {
                unsigned aoff = SWZ128((a_row + mt*16)*128 + kcol + a_colb);
                unsigned ah[4], al[4];
                ldsm4(ah[0], ah[1], ah[2], ah[3], bb + SM_AHI + aoff);
                ldsm4(al[0], al[1], al[2], al[3], bb + SM_ALO + aoff);
#pragma unroll
                for (int nt = 0; nt < 4; nt++) {
                    mma16816(acc[mt][nt], ah, &bh[nt*2]);   // wh*xh
                    mma16816(acc[mt][nt], ah, &bl[nt*2]);   // wh*xl
                    mma16816(acc[mt][nt], al, &bh[nt*2]);   // wl*xh
                }
            }
        }
    }

    // ---- epilogue: /64, +bias, relu, store ----
    const int mrow = lane >> 2;           // 0..7
    const int ncol = (lane & 3) * 2;      // 0,2,4,6
#pragma unroll
    for (int mt = 0; mt < 4; mt++) {
        const int ocA = ot*128 + wm*64 + mt*16 + mrow;
        const int ocB = ocA + 8;
        const float biasA = b1[ocA];
        const float biasB = b1[ocB];
#pragma unroll
        for (int nt = 0; nt < 4; nt++) {
            const int pos = pos0 + wn*32 + nt*8 + ncol;
            float v0 = acc[mt][nt][0] * W_INV + biasA;
            float v1 = acc[mt][nt][1] * W_INV + biasA;
            float v2 = acc[mt][nt][2] * W_INV + biasB;
            float v3 = acc[mt][nt][3] * W_INV + biasB;
            v0 = v0 > 0.f ? v0 : 0.f;
            v1 = v1 > 0.f ? v1 : 0.f;
            v2 = v2 > 0.f ? v2 : 0.f;
            v3 = v3 > 0.f ? v3 : 0.f;
            *reinterpret_cast<float2*>(
                g_hidden + ((size_t)img*CIN + ocA)*NPOS + pos) = make_float2(v0, v1);
            *reinterpret_cast<float2*>(
                g_hidden + ((size_t)img*CIN + ocB)*NPOS + pos) = make_float2(v2, v3);
        }
    }
}

// =================================================================
// 1x1 convs: output-split (3 groups of 18), channel order strictly
// sequential c=0..511 per output -> bit-identical to the R8 kernel.
// block 384 thr = 128 pos x 3 o-groups; grid (NPOS/128, N_IMG)
// =================================================================
__global__ __launch_bounds__(384) void conv1x1_kernel(
    const float* __restrict__ Wl, const float* __restrict__ bl,
    const float* __restrict__ Ws, const float* __restrict__ bs,
    float* __restrict__ out)
{
    __shared__ float Wc[64][NOUT];
    const int tid = threadIdx.x;
    const int lp  = tid & 127;            // pos lane
    const int og  = tid >> 7;             // o-group 0..2
    const int o0  = og * 18;
    const int img = blockIdx.y;
    const int pos = blockIdx.x * 128 + lp;

    float acc[18];
#pragma unroll
    for (int o = 0; o < 18; o++) acc[o] = 0.f;

    const float* hid = g_hidden + (size_t)img * CIN * NPOS;

    for (int c0 = 0; c0 < CIN; c0 += 64) {
        for (int idx = tid; idx < 64*NOUT; idx += 384) {
            int c = idx / NOUT;
            int o = idx - c*NOUT;
            Wc[c][o] = (o < 36) ? Wl[(size_t)o*CIN + c0 + c]
                                : Ws[(size_t)(o-36)*CIN + c0 + c];
        }
        __syncthreads();
#pragma unroll 4
        for (int c = 0; c < 64; c++) {
            float h = hid[(size_t)(c0+c)*NPOS + pos];
#pragma unroll
            for (int o = 0; o < 18; o++) acc[o] += h * Wc[c][o0 + o];
        }
        __syncthreads();
    }

#pragma unroll
    for (int o = 0; o < 18; o++) {
        int oo = o0 + o;
        if (oo < 36)
            out[OFF_LOCS + (size_t)img*A_TOT*4 + (size_t)pos*36 + oo] = acc[o] + bl[oo];
        else
            out[OFF_SCORES + (size_t)img*A_TOT*2 + (size_t)pos*18 + (oo-36)] = acc[o] + bs[oo-36];
    }
}

// =================================================================
// anchor generation into d_out anchor region
// =================================================================
__global__ void anchor_kernel(float* __restrict__ out)
{
    int i = blockIdx.x * blockDim.x + threadIdx.x;
    if (i >= A_TOT) return;
    int a   = i % 9;
    int pos = i / 9;
    int y = pos / WW, x = pos % WW;
    int ri = a / 3, si = a % 3;
    double rr = (ri == 0) ? 0.5 : (ri == 1 ? 1.0 : 2.0);
    double ss = (si == 0) ? 8.0 : (si == 1 ? 16.0 : 32.0);
    double h = 16.0 * ss * sqrt(rr);
    double w = 16.0 * ss * sqrt(1.0 / rr);
    float ymin = (float)(8.0 - h*0.5);
    float xmin = (float)(8.0 - w*0.5);
    float ymax = (float)(8.0 + h*0.5);
    float xmax = (float)(8.0 + w*0.5);
    float sy = (float)y * 16.0f, sx = (float)x * 16.0f;
    reinterpret_cast<float4*>(out + OFF_ANCHOR)[i] =
        make_float4(sy + ymin, sx + xmin, sy + ymax, sx + xmax);
}

// =================================================================
// proposal: loc2bbox + clip + min-size filter + fg softmax + sort key
// =================================================================
__device__ __forceinline__ float read_dim(const void* p)
{
    int v = *(const int*)p;
    if (v > 0 && v < (1 << 20)) return (float)v;   // plausibly int32
    return *(const float*)p;                        // else float bits
}

__global__ void proposal_kernel(const float* __restrict__ out,
                                const void* __restrict__ p_ih,
                                const void* __restrict__ p_iw)
{
    int t = blockIdx.x * blockDim.x + threadIdx.x;
    int img = t >> 16;          // / 65536
    int i   = t & (SORT_N - 1);
    if (img >= N_IMG) return;
    if (i >= A_TOT) { g_keys[t] = ~0ULL; return; }

    const float4 anc = reinterpret_cast<const float4*>(out + OFF_ANCHOR)[i];
    const float* loc = out + OFF_LOCS + (size_t)img*A_TOT*4 + (size_t)i*4;
    const float l0 = loc[0], l1 = loc[1], l2 = loc[2], l3 = loc[3];
    const float* sc = out + OFF_SCORES + (size_t)img*A_TOT*2 + (size_t)i*2;
    const float s0 = sc[0], s1 = sc[1];

    float h  = anc.z - anc.x, w = anc.w - anc.y;
    float cy = anc.x + 0.5f*h, cx = anc.y + 0.5f*w;
    float ncy = l0*h + cy, ncx = l1*w + cx;
    float nh  = expf(l2)*h,  nw  = expf(l3)*w;

    float fh = read_dim(p_ih), fw = read_dim(p_iw);
    float y1 = fminf(fmaxf(ncy - 0.5f*nh, 0.f), fh);
    float x1 = fminf(fmaxf(ncx - 0.5f*nw, 0.f), fw);
    float y2 = fminf(fmaxf(ncy + 0.5f*nh, 0.f), fh);
    float x2 = fminf(fmaxf(ncx + 0.5f*nw, 0.f), fw);

    bool ok = ((y2 - y1) >= MIN_SIZE) && ((x2 - x1) >= MIN_SIZE);

    float m  = fmaxf(s0, s1);
    float e0 = expf(s0 - m), e1 = expf(s1 - m);
    float fg = e1 / (e0 + e1);
    float score = ok ? fg : -INFINITY;

    g_rois_all[(size_t)img*A_TOT + i] = make_float4(y1, x1, y2, x2);

    unsigned u    = __float_as_uint(score);
    unsigned mkey = u ^ ((u >> 31) ? 0xFFFFFFFFu : 0x80000000u);   // ascending map
    unsigned dkey = ~mkey;                                          // descending
    g_keys[(size_t)img*SORT_N + i] = ((unsigned long long)dkey << 32) | (unsigned)i;
}

// =================================================================
// bitonic sort, 64-bit keys, 65536 elems per image, 4 images
// =================================================================
#define CHUNK 2048
__global__ __launch_bounds__(1024) void bitonic_local(int kstart, int fullsort)
{
    __shared__ unsigned long long sk[CHUNK];
    const int chunk = blockIdx.x;                       // 0..127
    unsigned long long* K = g_keys + (size_t)chunk * CHUNK;
    const int gbase = (chunk & 31) * CHUNK;             // index within image
    const int tid = threadIdx.x;

    sk[tid]        = K[tid];
    sk[tid + 1024] = K[tid + 1024];
    __syncthreads();

    if (fullsort) {
        for (int k = 2; k <= CHUNK; k <<= 1) {
            for (int j = k >> 1; j > 0; j >>= 1) {
                int i   = ((tid & ~(j - 1)) << 1) | (tid & (j - 1));
                int ixj = i | j;
                bool up = (((gbase + i) & k) == 0);
                unsigned long long a = sk[i], b = sk[ixj];
                if ((a > b) == up) { sk[i] = b; sk[ixj] = a; }
                __syncthreads();
            }
        }
    } else {
        const int k = kstart;
        for (int j = 1024; j > 0; j >>= 1) {
            int i   = ((tid & ~(j - 1)) << 1) | (tid & (j - 1));
            int ixj = i | j;
            bool up = (((gbase + i) & k) == 0);
            unsigned long long a = sk[i], b = sk[ixj];
            if ((a > b) == up) { sk[i] = b; sk[ixj] = a; }
            __syncthreads();
        }
    }
    K[tid]        = sk[tid];
    K[tid + 1024] = sk[tid + 1024];
}

__global__ void bitonic_global_step(int k, int j)
{
    int t   = blockIdx.x * blockDim.x + threadIdx.x;   // 4 * 32768
    int img = t >> 15;
    int tt  = t & 32767;
    int i   = ((tt & ~(j - 1)) << 1) | (tt & (j - 1));
    int ixj = i | j;
    unsigned long long* K = g_keys + (size_t)img * SORT_N;
    unsigned long long a = K[i], b = K[ixj];
    bool up = ((i & k) == 0);
    if ((a > b) == up) { K[i] = b; K[ixj] = a; }
}

// =================================================================
// gather top-3000 boxes + scores
// =================================================================
__global__ void gather_kernel()
{
    int t = blockIdx.x * blockDim.x + threadIdx.x;
    if (t >= N_IMG * PRE_NMS) return;
    int img = t / PRE_NMS;
    int i   = t - img * PRE_NMS;
    unsigned long long key = g_keys[(size_t)img*SORT_N + i];
    unsigned idx = (unsigned)(key & 0xFFFFFFFFu);
    g_boxes_top[t] = g_rois_all[(size_t)img*A_TOT + idx];
    unsigned dkey = (unsigned)(key >> 32);
    unsigned mkey = ~dkey;
    unsigned u = (mkey & 0x80000000u) ? (mkey ^ 0x80000000u) : ~mkey;
    g_scores_top[t] = __uint_as_float(u);
}

// =================================================================
// NMS suppression bitmask (3000 x 3000, only j > i bits)
// =================================================================
__global__ __launch_bounds__(64) void mask_kernel()
{
    const int img  = blockIdx.z;
    const int rowb = blockIdx.y * 64;
    const int colb = blockIdx.x * 64;
    __shared__ float4 cb[64];
    const int t = threadIdx.x;
    int col0 = colb + t;
    cb[t] = (col0 < PRE_NMS) ? g_boxes_top[(size_t)img*PRE_NMS + col0]
                             : make_float4(0.f, 0.f, 0.f, 0.f);
    __syncthreads();

    int row = rowb + t;
    if (row >= PRE_NMS) return;
    float4 rb = g_boxes_top[(size_t)img*PRE_NMS + row];
    float ra = fmaxf(rb.z - rb.x, 0.f) * fmaxf(rb.w - rb.y, 0.f);

    unsigned w0 = 0, w1 = 0;
#pragma unroll 4
    for (int c = 0; c < 64; c++) {
        int col = colb + c;
        if (col >= PRE_NMS || col <= row) continue;
        float4 b = cb[c];
        float yy1 = fmaxf(rb.x, b.x), xx1 = fmaxf(rb.y, b.y);
        float yy2 = fminf(rb.z, b.z), xx2 = fminf(rb.w, b.w);
        float inter = fmaxf(yy2 - yy1, 0.f) * fmaxf(xx2 - xx1, 0.f);
        float ba = fmaxf(b.z - b.x, 0.f) * fmaxf(b.w - b.y, 0.f);
        float iou = inter / (ra + ba - inter + 1e-9f);
        if (iou > NMS_THRESH) {
            if (c < 32) w0 |= 1u << c; else w1 |= 1u << (c - 32);
        }
    }
    unsigned* mrow = g_mask + ((size_t)img*PRE_NMS + row) * NMS_WORDS;
    int wi = colb >> 5;
    mrow[wi] = w0;
    if (wi + 1 < NMS_WORDS) mrow[wi + 1] = w1;
}

// =================================================================
// zero rois region + write roi_indices
// =================================================================
__global__ void fill_kernel(float* __restrict__ out)
{
    int t = blockIdx.x * blockDim.x + threadIdx.x;
    if (t < SZ_ROIS) out[OFF_ROIS + t] = 0.f;
    else if (t < SZ_ROIS + SZ_RIDX) {
        int i = t - SZ_ROIS;
        out[OFF_RIDX + i] = (float)(i / POST_NMS);
    }
}

// =================================================================
// sequential greedy NMS scan (1 warp per image), write kept rois
// =================================================================
__global__ void scan_kernel(float* __restrict__ out)
{
    const int img  = blockIdx.x;
    const int lane = threadIdx.x;

    unsigned sup0, sup1, sup2;
    {
        unsigned v[3];
#pragma unroll
        for (int s = 0; s < 3; s++) {
            unsigned vv = 0;
            int w = s*32 + lane;
            for (int b = 0; b < 32; b++) {
                int i = w*32 + b;
                if (i < PRE_NMS && g_scores_top[(size_t)img*PRE_NMS + i] == -INFINITY)
                    vv |= 1u << b;
            }
            v[s] = vv;
        }
        sup0 = v[0]; sup1 = v[1]; sup2 = v[2];
    }

    int keep = 0;
    const unsigned* maskbase = g_mask + (size_t)img*PRE_NMS*NMS_WORDS;

    for (int i = 0; i < PRE_NMS; i++) {
        int w = i >> 5, b = i & 31;
        int slot = w >> 5, owner = w & 31;
        unsigned myw = (slot == 0) ? sup0 : (slot == 1 ? sup1 : sup2);
        unsigned word = __shfl_sync(0xFFFFFFFFu, myw, owner);
        if (!((word >> b) & 1u)) {
            if (keep < POST_NMS && lane == 0) {
                float4 bx = g_boxes_top[(size_t)img*PRE_NMS + i];
                float* o = out + OFF_ROIS + ((size_t)img*POST_NMS + keep)*4;
                o[0] = bx.x; o[1] = bx.y; o[2] = bx.z; o[3] = bx.w;
            }
            keep++;
            const unsigned* mrow = maskbase + (size_t)i * NMS_WORDS;
            int w0i = lane, w1i = 32 + lane, w2i = 64 + lane;
            if (w0i < NMS_WORDS) sup0 |= mrow[w0i];
            if (w1i < NMS_WORDS) sup1 |= mrow[w1i];
            if (w2i < NMS_WORDS) sup2 |= mrow[w2i];
        }
    }
}

// =================================================================
// launch
// =================================================================
extern "C" void kernel_launch(void* const* d_in, const int* in_sizes, int n_in,
                              void* d_out, int out_size)
{
    const float* x   = (const float*)d_in[0];
    const void*  ih  = d_in[1];
    const void*  iw  = d_in[2];
    const float* W1  = (const float*)d_in[3];
    const float* b1  = (const float*)d_in[4];
    const float* Ws  = (const float*)d_in[5];
    const float* bs  = (const float*)d_in[6];
    const float* Wl  = (const float*)d_in[7];
    const float* bl  = (const float*)d_in[8];
    float* out = (float*)d_out;

    static int smem_set = 0;
    if (!smem_set) {
        cudaFuncSetAttribute(conv_hmma_kernel,
                             cudaFuncAttributeMaxDynamicSharedMemorySize,
                             SM_CONV_TOTAL);
        smem_set = 1;
    }

    // weight split/pre-swizzle (x64 scale)
    wprep_kernel<<<(4*NCHUNK*128*32 + 255)/256, 256>>>(W1);
    // x split + transpose to fp16 hi/lo
    xsplit_kernel<<<dim3(NPOS/32, CIN/32, N_IMG), dim3(32, 8)>>>(x);
    // HMMA split-fp16 3x3 conv + relu (3-stage cp.async ring)
    conv_hmma_kernel<<<dim3(4, 32, N_IMG), 256, SM_CONV_TOTAL>>>(b1);
    // 1x1 heads -> d_out locs/scores (output-split, order-preserving)
    conv1x1_kernel<<<dim3(NPOS/128, N_IMG), 384>>>(Wl, bl, Ws, bs, out);
    // anchors -> d_out anchor region
    anchor_kernel<<<(A_TOT + 255)/256, 256>>>(out);
    // zero rois + roi indices
    fill_kernel<<<(SZ_ROIS + SZ_RIDX + 255)/256, 256>>>(out);
    // proposals + sort keys
    proposal_kernel<<<(N_IMG*SORT_N)/256, 256>>>(out, ih, iw);

    // bitonic sort (descending score, ascending index ties)
    bitonic_local<<<128, 1024>>>(0, 1);
    for (int k = 4096; k <= SORT_N; k <<= 1) {
        for (int j = k >> 1; j >= CHUNK; j >>= 1)
            bitonic_global_step<<<(N_IMG*SORT_N/2)/256, 256>>>(k, j);
        bitonic_local<<<128, 1024>>>(k, 0);
    }

    // top-3000 gather
    gather_kernel<<<(N_IMG*PRE_NMS + 255)/256, 256>>>();
    // IoU bitmask
    mask_kernel<<<dim3(47, 47, N_IMG), 64>>>();
    // sequential NMS scan -> rois
    scan_kernel<<<N_IMG, 32>>>(out);
}